// round 1
// baseline (speedup 1.0000x reference)
#include <cuda_runtime.h>
#include <math.h>

#define T_TOKENS 16384
#define D_MODEL  2048
#define E_EXP    8
#define NKAN     2
#define DD       256    // per-expert width d
#define HH       1024   // hidden H
#define MT       64     // token tile per CTA
#define HK       64     // H chunk per iteration

// smem layout (floats)
#define XS_OFF   0
#define XS_SZ    (256*64)        // xsT[k(256)][row(64)]
#define WS1_OFF  (XS_OFF + XS_SZ)
#define WS1_SZ   (64*64)         // ws1[k(64)][col(64)]
#define WS2_OFF  (WS1_OFF + WS1_SZ)
#define WS2_SZ   (32*256)        // ws2[k(32)][col(256)]
#define AST_OFF  (WS2_OFF + WS2_SZ)
#define AST_PITCH 68
#define AST_SZ   (192*AST_PITCH) // asT[k(<=192)][row(64)+pad]
#define SMEM_FLOATS (AST_OFF + AST_SZ)
#define SMEM_BYTES  (SMEM_FLOATS * 4)

__device__ float g_c0[NKAN * DD];

// c0[e][o] = sum_h kan_poly_w[e][p=0][h][o] + kan_bias[e][o]   (T0 == ones matrix)
__global__ void c0_kernel(const float* __restrict__ kan_poly_w,
                          const float* __restrict__ kan_bias) {
    int e = blockIdx.x;
    int o = threadIdx.x;
    const float* w0 = kan_poly_w + (size_t)e * 4 * HH * DD;   // p = 0 plane
    float s = kan_bias[e * DD + o];
    for (int h = 0; h < HH; ++h) s += w0[(size_t)h * DD + o];
    g_c0[e * DD + o] = s;
}

__device__ __forceinline__ float gelu_tanh(float v) {
    float u = 0.7978845608028654f * (v + 0.044715f * v * v * v);
    return 0.5f * v * (1.0f + tanhf(u));
}

__global__ void __launch_bounds__(256, 1)
ffn_kernel(const float* __restrict__ x,
           const float* __restrict__ kan_lin_w,
           const float* __restrict__ kan_poly_w,
           const float* __restrict__ mlp_w1,
           const float* __restrict__ mlp_b1,
           const float* __restrict__ mlp_w2,
           const float* __restrict__ mlp_b2,
           float* __restrict__ out) {
    extern __shared__ float sm[];
    float* xsT = sm + XS_OFF;
    float* ws1 = sm + WS1_OFF;
    float* ws2 = sm + WS2_OFF;
    float* asT = sm + AST_OFF;

    const int e   = blockIdx.y;
    const int t0  = blockIdx.x * MT;
    const int tid = threadIdx.x;
    const int tx  = tid & 15;   // output-col group
    const int ty  = tid >> 4;   // token-row group
    const bool isKan = (e < NKAN);
    const int  m  = e - NKAN;
    const int  nq = isKan ? 6 : 2;   // 32-row K-tiles per chunk in GEMM2

    const float* W1 = isKan ? (kan_lin_w + (size_t)e * DD * HH)
                            : (mlp_w1    + (size_t)m * DD * HH);

    // ---- load x tile transposed into smem: xsT[k][row] ----
    {
        int r = tid & 63;           // token row in tile
        int cseg = tid >> 6;        // 0..3, 64-col segment
        const float* xrow = x + (size_t)(t0 + r) * D_MODEL + e * DD + cseg * 64;
        #pragma unroll
        for (int it = 0; it < 16; ++it) {
            float4 v = *(const float4*)(xrow + it * 4);
            int k = cseg * 64 + it * 4;
            xsT[(k + 0) * 64 + r] = v.x;
            xsT[(k + 1) * 64 + r] = v.y;
            xsT[(k + 2) * 64 + r] = v.z;
            xsT[(k + 3) * 64 + r] = v.w;
        }
    }

    // ---- init output accumulator with bias (T0-term+kan_bias for KAN, b2 for MLP) ----
    float c2[4][16];
    {
        const float* bias = isKan ? (g_c0 + e * DD) : (mlp_b2 + m * DD);
        #pragma unroll
        for (int g = 0; g < 4; ++g)
            #pragma unroll
            for (int ci = 0; ci < 4; ++ci) {
                float bv = bias[g * 64 + tx * 4 + ci];
                #pragma unroll
                for (int ri = 0; ri < 4; ++ri) c2[ri][g * 4 + ci] = bv;
            }
    }

    for (int j = 0; j < HH / HK; ++j) {
        // ================= GEMM1: Hc[64x64] = x_tile[64x256] @ W1[:, j*64..] =======
        float hc[4][4];
        #pragma unroll
        for (int ri = 0; ri < 4; ++ri)
            #pragma unroll
            for (int ci = 0; ci < 4; ++ci) hc[ri][ci] = 0.f;

        for (int kt = 0; kt < 4; ++kt) {
            __syncthreads();
            const int kk = kt * 64;
            // stage ws1: W1 rows kk..kk+63, cols j*64..j*64+63
            #pragma unroll
            for (int it = 0; it < 4; ++it) {
                int idx = it * 256 + tid;        // 0..1023
                int row = idx >> 4, seg = idx & 15;
                *(float4*)(ws1 + row * 64 + seg * 4) =
                    *(const float4*)(W1 + (size_t)(kk + row) * HH + j * 64 + seg * 4);
            }
            __syncthreads();
            #pragma unroll 16
            for (int k = 0; k < 64; ++k) {
                float4 a4 = *(const float4*)(xsT + (kk + k) * 64 + ty * 4);
                float4 b4 = *(const float4*)(ws1 + k * 64 + tx * 4);
                float av[4] = {a4.x, a4.y, a4.z, a4.w};
                float bv[4] = {b4.x, b4.y, b4.z, b4.w};
                #pragma unroll
                for (int ri = 0; ri < 4; ++ri)
                    #pragma unroll
                    for (int ci = 0; ci < 4; ++ci)
                        hc[ri][ci] = fmaf(av[ri], bv[ci], hc[ri][ci]);
            }
        }

        // ================= activation -> asT (transposed) ==========================
        if (isKan) {
            #pragma unroll
            for (int ri = 0; ri < 4; ++ri)
                #pragma unroll
                for (int ci = 0; ci < 4; ++ci) {
                    int c = tx * 4 + ci;
                    int r = ty * 4 + ri;
                    float t1 = tanhf(hc[ri][ci]);
                    float t2 = 2.f * t1 * t1 - 1.f;
                    float t3 = 2.f * t1 * t2 - t1;
                    asT[(c      ) * AST_PITCH + r] = t1;
                    asT[(c +  64) * AST_PITCH + r] = t2;
                    asT[(c + 128) * AST_PITCH + r] = t3;
                }
        } else {
            float b1v[4];
            #pragma unroll
            for (int ci = 0; ci < 4; ++ci)
                b1v[ci] = mlp_b1[(size_t)m * HH + j * 64 + tx * 4 + ci];
            #pragma unroll
            for (int ri = 0; ri < 4; ++ri)
                #pragma unroll
                for (int ci = 0; ci < 4; ++ci) {
                    int c = tx * 4 + ci;
                    int r = ty * 4 + ri;
                    asT[c * AST_PITCH + r] = gelu_tanh(hc[ri][ci] + b1v[ci]);
                }
        }

        // ================= GEMM2: out[64x256] += act[64 x 64*np] @ W2chunk =========
        for (int q = 0; q < nq; ++q) {
            __syncthreads();   // asT writes visible / ws2 reusable
            const float* W2row;
            if (isKan)
                W2row = kan_poly_w +
                        (((size_t)e * 4 + 1 + (q >> 1)) * HH + j * 64 + (q & 1) * 32) * DD;
            else
                W2row = mlp_w2 + ((size_t)m * HH + j * 64 + q * 32) * DD;
            // stage ws2: 32 rows x 256 cols
            #pragma unroll
            for (int it = 0; it < 8; ++it) {
                int idx = it * 256 + tid;        // 0..2047
                int row = idx >> 6, seg = idx & 63;
                *(float4*)(ws2 + row * 256 + seg * 4) =
                    *(const float4*)(W2row + (size_t)row * DD + seg * 4);
            }
            __syncthreads();
            #pragma unroll 8
            for (int r = 0; r < 32; ++r) {
                float4 a4 = *(const float4*)(asT + (q * 32 + r) * AST_PITCH + ty * 4);
                float av[4] = {a4.x, a4.y, a4.z, a4.w};
                #pragma unroll
                for (int g = 0; g < 4; ++g) {
                    float4 b4 = *(const float4*)(ws2 + r * 256 + g * 64 + tx * 4);
                    float bv[4] = {b4.x, b4.y, b4.z, b4.w};
                    #pragma unroll
                    for (int ri = 0; ri < 4; ++ri)
                        #pragma unroll
                        for (int ci = 0; ci < 4; ++ci)
                            c2[ri][g * 4 + ci] = fmaf(av[ri], bv[ci], c2[ri][g * 4 + ci]);
                }
            }
        }
    }

    // ---- write output tile ----
    #pragma unroll
    for (int ri = 0; ri < 4; ++ri) {
        float* orow = out + (size_t)(t0 + ty * 4 + ri) * D_MODEL + e * DD;
        #pragma unroll
        for (int g = 0; g < 4; ++g) {
            float4 v;
            v.x = c2[ri][g * 4 + 0];
            v.y = c2[ri][g * 4 + 1];
            v.z = c2[ri][g * 4 + 2];
            v.w = c2[ri][g * 4 + 3];
            *(float4*)(orow + g * 64 + tx * 4) = v;
        }
    }
}

extern "C" void kernel_launch(void* const* d_in, const int* in_sizes, int n_in,
                              void* d_out, int out_size) {
    const float* x   = (const float*)d_in[0];
    const float* klw = (const float*)d_in[1];
    const float* kpw = (const float*)d_in[2];
    const float* kb  = (const float*)d_in[3];
    const float* w1  = (const float*)d_in[4];
    const float* b1  = (const float*)d_in[5];
    const float* w2  = (const float*)d_in[6];
    const float* b2  = (const float*)d_in[7];
    float* out = (float*)d_out;

    cudaFuncSetAttribute(ffn_kernel, cudaFuncAttributeMaxDynamicSharedMemorySize,
                         SMEM_BYTES);

    c0_kernel<<<NKAN, DD>>>(kpw, kb);
    ffn_kernel<<<dim3(T_TOKENS / MT, E_EXP), 256, SMEM_BYTES>>>(
        x, klw, kpw, w1, b1, w2, b2, out);
}

// round 2
// speedup vs baseline: 1.0000x; 1.0000x over previous
#include <cuda_runtime.h>
#include <math.h>

#define T_TOKENS 16384
#define D_MODEL  2048
#define E_EXP    8
#define NKAN     2
#define DD       256    // per-expert width d
#define HH       1024   // hidden H
#define MT       64     // token tile per CTA
#define HK       64     // H chunk per iteration

// smem layout (floats)
#define XS_OFF   0
#define XS_SZ    (256*64)        // xsT[k(256)][row(64)]
#define WS1_OFF  (XS_OFF + XS_SZ)
#define WS1_SZ   (64*64)         // ws1[k(64)][col(64)]
#define WS2_OFF  (WS1_OFF + WS1_SZ)
#define WS2_SZ   (32*256)        // ws2[k(32)][col(256)]
#define AST_OFF  (WS2_OFF + WS2_SZ)
#define AST_PITCH 68
#define AST_SZ   (192*AST_PITCH) // asT[k(<=192)][row(64)+pad]
#define SMEM_FLOATS (AST_OFF + AST_SZ)
#define SMEM_BYTES  (SMEM_FLOATS * 4)

__device__ float g_c0[NKAN * DD];

// c0[e][o] = sum_h kan_poly_w[e][p=0][h][o] + kan_bias[e][o]   (T0 == ones matrix)
__global__ void c0_kernel(const float* __restrict__ kan_poly_w,
                          const float* __restrict__ kan_bias) {
    int e = blockIdx.x;
    int o = threadIdx.x;
    const float* w0 = kan_poly_w + (size_t)e * 4 * HH * DD;   // p = 0 plane
    float s = kan_bias[e * DD + o];
    for (int h = 0; h < HH; ++h) s += w0[(size_t)h * DD + o];
    g_c0[e * DD + o] = s;
}

__device__ __forceinline__ float gelu_tanh(float v) {
    float u = 0.7978845608028654f * (v + 0.044715f * v * v * v);
    return 0.5f * v * (1.0f + tanhf(u));
}

__global__ void __launch_bounds__(256, 1)
ffn_kernel(const float* __restrict__ x,
           const float* __restrict__ kan_lin_w,
           const float* __restrict__ kan_poly_w,
           const float* __restrict__ mlp_w1,
           const float* __restrict__ mlp_b1,
           const float* __restrict__ mlp_w2,
           const float* __restrict__ mlp_b2,
           float* __restrict__ out) {
    extern __shared__ float sm[];
    float* xsT = sm + XS_OFF;
    float* ws1 = sm + WS1_OFF;
    float* ws2 = sm + WS2_OFF;
    float* asT = sm + AST_OFF;

    const int e   = blockIdx.y;
    const int t0  = blockIdx.x * MT;
    const int tid = threadIdx.x;
    const int tx  = tid & 15;   // output-col group
    const int ty  = tid >> 4;   // token-row group
    const bool isKan = (e < NKAN);
    const int  m  = e - NKAN;
    const int  nq = isKan ? 6 : 2;   // 32-row K-tiles per chunk in GEMM2

    const float* W1 = isKan ? (kan_lin_w + (size_t)e * DD * HH)
                            : (mlp_w1    + (size_t)m * DD * HH);

    // ---- load x tile transposed into smem: xsT[k][row] ----
    {
        int r = tid & 63;           // token row in tile
        int cseg = tid >> 6;        // 0..3, 64-col segment
        const float* xrow = x + (size_t)(t0 + r) * D_MODEL + e * DD + cseg * 64;
        #pragma unroll
        for (int it = 0; it < 16; ++it) {
            float4 v = *(const float4*)(xrow + it * 4);
            int k = cseg * 64 + it * 4;
            xsT[(k + 0) * 64 + r] = v.x;
            xsT[(k + 1) * 64 + r] = v.y;
            xsT[(k + 2) * 64 + r] = v.z;
            xsT[(k + 3) * 64 + r] = v.w;
        }
    }

    // ---- init output accumulator with bias (T0-term+kan_bias for KAN, b2 for MLP) ----
    float c2[4][16];
    {
        const float* bias = isKan ? (g_c0 + e * DD) : (mlp_b2 + m * DD);
        #pragma unroll
        for (int g = 0; g < 4; ++g)
            #pragma unroll
            for (int ci = 0; ci < 4; ++ci) {
                float bv = bias[g * 64 + tx * 4 + ci];
                #pragma unroll
                for (int ri = 0; ri < 4; ++ri) c2[ri][g * 4 + ci] = bv;
            }
    }

    for (int j = 0; j < HH / HK; ++j) {
        // ================= GEMM1: Hc[64x64] = x_tile[64x256] @ W1[:, j*64..] =======
        float hc[4][4];
        #pragma unroll
        for (int ri = 0; ri < 4; ++ri)
            #pragma unroll
            for (int ci = 0; ci < 4; ++ci) hc[ri][ci] = 0.f;

        for (int kt = 0; kt < 4; ++kt) {
            __syncthreads();
            const int kk = kt * 64;
            // stage ws1: W1 rows kk..kk+63, cols j*64..j*64+63
            #pragma unroll
            for (int it = 0; it < 4; ++it) {
                int idx = it * 256 + tid;        // 0..1023
                int row = idx >> 4, seg = idx & 15;
                *(float4*)(ws1 + row * 64 + seg * 4) =
                    *(const float4*)(W1 + (size_t)(kk + row) * HH + j * 64 + seg * 4);
            }
            __syncthreads();
            #pragma unroll 16
            for (int k = 0; k < 64; ++k) {
                float4 a4 = *(const float4*)(xsT + (kk + k) * 64 + ty * 4);
                float4 b4 = *(const float4*)(ws1 + k * 64 + tx * 4);
                float av[4] = {a4.x, a4.y, a4.z, a4.w};
                float bv[4] = {b4.x, b4.y, b4.z, b4.w};
                #pragma unroll
                for (int ri = 0; ri < 4; ++ri)
                    #pragma unroll
                    for (int ci = 0; ci < 4; ++ci)
                        hc[ri][ci] = fmaf(av[ri], bv[ci], hc[ri][ci]);
            }
        }

        // ================= activation -> asT (transposed) ==========================
        if (isKan) {
            #pragma unroll
            for (int ri = 0; ri < 4; ++ri)
                #pragma unroll
                for (int ci = 0; ci < 4; ++ci) {
                    int c = tx * 4 + ci;
                    int r = ty * 4 + ri;
                    float t1 = tanhf(hc[ri][ci]);
                    float t2 = 2.f * t1 * t1 - 1.f;
                    float t3 = 2.f * t1 * t2 - t1;
                    asT[(c      ) * AST_PITCH + r] = t1;
                    asT[(c +  64) * AST_PITCH + r] = t2;
                    asT[(c + 128) * AST_PITCH + r] = t3;
                }
        } else {
            float b1v[4];
            #pragma unroll
            for (int ci = 0; ci < 4; ++ci)
                b1v[ci] = mlp_b1[(size_t)m * HH + j * 64 + tx * 4 + ci];
            #pragma unroll
            for (int ri = 0; ri < 4; ++ri)
                #pragma unroll
                for (int ci = 0; ci < 4; ++ci) {
                    int c = tx * 4 + ci;
                    int r = ty * 4 + ri;
                    asT[c * AST_PITCH + r] = gelu_tanh(hc[ri][ci] + b1v[ci]);
                }
        }

        // ================= GEMM2: out[64x256] += act[64 x 64*np] @ W2chunk =========
        for (int q = 0; q < nq; ++q) {
            __syncthreads();   // asT writes visible / ws2 reusable
            const float* W2row;
            if (isKan)
                W2row = kan_poly_w +
                        (((size_t)e * 4 + 1 + (q >> 1)) * HH + j * 64 + (q & 1) * 32) * DD;
            else
                W2row = mlp_w2 + ((size_t)m * HH + j * 64 + q * 32) * DD;
            // stage ws2: 32 rows x 256 cols
            #pragma unroll
            for (int it = 0; it < 8; ++it) {
                int idx = it * 256 + tid;        // 0..2047
                int row = idx >> 6, seg = idx & 63;
                *(float4*)(ws2 + row * 256 + seg * 4) =
                    *(const float4*)(W2row + (size_t)row * DD + seg * 4);
            }
            __syncthreads();
            #pragma unroll 8
            for (int r = 0; r < 32; ++r) {
                float4 a4 = *(const float4*)(asT + (q * 32 + r) * AST_PITCH + ty * 4);
                float av[4] = {a4.x, a4.y, a4.z, a4.w};
                #pragma unroll
                for (int g = 0; g < 4; ++g) {
                    float4 b4 = *(const float4*)(ws2 + r * 256 + g * 64 + tx * 4);
                    float bv[4] = {b4.x, b4.y, b4.z, b4.w};
                    #pragma unroll
                    for (int ri = 0; ri < 4; ++ri)
                        #pragma unroll
                        for (int ci = 0; ci < 4; ++ci)
                            c2[ri][g * 4 + ci] = fmaf(av[ri], bv[ci], c2[ri][g * 4 + ci]);
                }
            }
        }
    }

    // ---- write output tile ----
    #pragma unroll
    for (int ri = 0; ri < 4; ++ri) {
        float* orow = out + (size_t)(t0 + ty * 4 + ri) * D_MODEL + e * DD;
        #pragma unroll
        for (int g = 0; g < 4; ++g) {
            float4 v;
            v.x = c2[ri][g * 4 + 0];
            v.y = c2[ri][g * 4 + 1];
            v.z = c2[ri][g * 4 + 2];
            v.w = c2[ri][g * 4 + 3];
            *(float4*)(orow + g * 64 + tx * 4) = v;
        }
    }
}

extern "C" void kernel_launch(void* const* d_in, const int* in_sizes, int n_in,
                              void* d_out, int out_size) {
    const float* x   = (const float*)d_in[0];
    const float* klw = (const float*)d_in[1];
    const float* kpw = (const float*)d_in[2];
    const float* kb  = (const float*)d_in[3];
    const float* w1  = (const float*)d_in[4];
    const float* b1  = (const float*)d_in[5];
    const float* w2  = (const float*)d_in[6];
    const float* b2  = (const float*)d_in[7];
    float* out = (float*)d_out;

    cudaFuncSetAttribute(ffn_kernel, cudaFuncAttributeMaxDynamicSharedMemorySize,
                         SMEM_BYTES);

    c0_kernel<<<NKAN, DD>>>(kpw, kb);
    ffn_kernel<<<dim3(T_TOKENS / MT, E_EXP), 256, SMEM_BYTES>>>(
        x, klw, kpw, w1, b1, w2, b2, out);
}

// round 4
// speedup vs baseline: 2.1262x; 2.1262x over previous
#include <cuda_runtime.h>
#include <cuda_bf16.h>
#include <math.h>
#include <stdint.h>

#define TOK    16384
#define DMODEL 2048
#define EEXP   8
#define NKAN   2
#define DD     256
#define HH     1024
#define MT     64

// ---------------- global scratch (bf16 hi/lo pre-splits) ----------------
__device__ __align__(16) __nv_bfloat16 g_xh[(size_t)TOK * DMODEL];
__device__ __align__(16) __nv_bfloat16 g_xl[(size_t)TOK * DMODEL];
__device__ __align__(16) __nv_bfloat16 g_w1h[(size_t)EEXP * HH * DD];   // [e][h][d]
__device__ __align__(16) __nv_bfloat16 g_w1l[(size_t)EEXP * HH * DD];
__device__ __align__(16) __nv_bfloat16 g_w2mh[(size_t)6 * DD * HH];     // [m][o][h]
__device__ __align__(16) __nv_bfloat16 g_w2ml[(size_t)6 * DD * HH];
__device__ __align__(16) __nv_bfloat16 g_w2kh[(size_t)6 * DD * HH];     // [e*3+p-1][o][h]
__device__ __align__(16) __nv_bfloat16 g_w2kl[(size_t)6 * DD * HH];
__device__ float g_c0[NKAN * DD];

// ---------------- smem layout (bytes) ----------------
#define PX     528      // X / W1 row pitch (256 bf16 = 512B + 16 pad)
#define PW2    144      // W2 / act row pitch (64 bf16 = 128B + 16 pad)
#define SM_XH  0
#define SM_XL  33792
#define SM_W1H 67584
#define SM_W1L 101376
#define SM_W2H 135168   // two halves of 128 rows each (18432 B per half)
#define SM_W2L 172032
#define SM_AH  208896
#define SM_AL  218112
#define SM_TOTAL 227328
#define DXL   33792     // XL - XH
#define DW1L  33792
#define DW2L  36864
#define DAL   9216

// ---------------- PTX helpers ----------------
__device__ __forceinline__ uint32_t smem_u32(const void* p) {
    uint32_t a;
    asm("{ .reg .u64 t; cvta.to.shared.u64 t, %1; cvt.u32.u64 %0, t; }" : "=r"(a) : "l"(p));
    return a;
}
__device__ __forceinline__ void cp16(uint32_t d, const void* s) {
    asm volatile("cp.async.cg.shared.global [%0], [%1], 16;" :: "r"(d), "l"(s));
}
#define CP_COMMIT() asm volatile("cp.async.commit_group;" ::: "memory")
#define CP_WAIT(N)  asm volatile("cp.async.wait_group %0;" :: "n"(N) : "memory")

__device__ __forceinline__ void ldsm4(uint32_t addr, uint32_t r[4]) {
    asm volatile("ldmatrix.sync.aligned.m8n8.x4.shared.b16 {%0,%1,%2,%3}, [%4];"
                 : "=r"(r[0]), "=r"(r[1]), "=r"(r[2]), "=r"(r[3]) : "r"(addr));
}
__device__ __forceinline__ void mma16816(float c[4], const uint32_t a[4],
                                         uint32_t b0, uint32_t b1) {
    asm volatile("mma.sync.aligned.m16n8k16.row.col.f32.bf16.bf16.f32 "
                 "{%0,%1,%2,%3}, {%4,%5,%6,%7}, {%8,%9}, {%0,%1,%2,%3};"
                 : "+f"(c[0]), "+f"(c[1]), "+f"(c[2]), "+f"(c[3])
                 : "r"(a[0]), "r"(a[1]), "r"(a[2]), "r"(a[3]), "r"(b0), "r"(b1));
}

__device__ __forceinline__ void packhl(float a, float b, uint32_t& h, uint32_t& l) {
    __nv_bfloat16 ha = __float2bfloat16(a), hb = __float2bfloat16(b);
    float la = a - __bfloat162float(ha), lb = b - __bfloat162float(hb);
    __nv_bfloat162 H, L;
    H.x = ha; H.y = hb;
    L.x = __float2bfloat16(la); L.y = __float2bfloat16(lb);
    h = *reinterpret_cast<uint32_t*>(&H);
    l = *reinterpret_cast<uint32_t*>(&L);
}
__device__ __forceinline__ float gelu_tanh(float v) {
    float u = 0.7978845608028654f * (v + 0.044715f * v * v * v);
    return 0.5f * v * (1.0f + tanhf(u));
}

// ---------------- staging (cp.async) ----------------
__device__ __forceinline__ void stage64(uint32_t dst, const __nv_bfloat16* src,
                                        int spitch, int tid) {
    const char* s = (const char*)src;
    #pragma unroll
    for (int i = 0; i < 8; ++i) {
        int idx = i * 256 + tid, r = idx >> 5, c = idx & 31;
        cp16(dst + r * PX + c * 16, s + (size_t)r * spitch + c * 16);
    }
}
__device__ __forceinline__ void stage128(uint32_t dst, const __nv_bfloat16* src, int tid) {
    const char* s = (const char*)src;   // src pitch = HH*2 = 2048 B
    #pragma unroll
    for (int i = 0; i < 4; ++i) {
        int idx = i * 256 + tid, r = idx >> 3, c = idx & 7;
        cp16(dst + r * PW2 + c * 16, s + (size_t)r * 2048 + c * 16);
    }
}
__device__ __forceinline__ void stage_w2(uint32_t sb, int j, int s, bool isKan,
                                         int e, int m, int tid) {
    int half = s & 1;
    size_t off;
    const __nv_bfloat16 *sh, *sl;
    if (isKan) {
        off = ((size_t)(e * 3 + (s >> 1)) * DD + half * 128) * HH + j * 64;
        sh = g_w2kh + off; sl = g_w2kl + off;
    } else {
        off = ((size_t)m * DD + half * 128) * HH + j * 64;
        sh = g_w2mh + off; sl = g_w2ml + off;
    }
    uint32_t d = sb + SM_W2H + half * 18432;
    stage128(d, sh, tid);
    stage128(d + DW2L, sl, tid);
}

// ---------------- prologue kernels ----------------
__global__ void c0_kernel(const float* __restrict__ kpw, const float* __restrict__ kb) {
    int e = blockIdx.x, o = threadIdx.x;
    const float* w0 = kpw + (size_t)e * 4 * HH * DD;
    float s = kb[e * DD + o];
    for (int h = 0; h < HH; ++h) s += w0[(size_t)h * DD + o];
    g_c0[e * DD + o] = s;
}
__global__ void xsplit(const float* __restrict__ x) {
    size_t i = ((size_t)blockIdx.x * 256 + threadIdx.x) * 4;
    float4 v = *(const float4*)(x + i);
    float vv[4] = {v.x, v.y, v.z, v.w};
    __nv_bfloat162 H0, H1, L0, L1;
    __nv_bfloat16 h0 = __float2bfloat16(vv[0]), h1 = __float2bfloat16(vv[1]);
    __nv_bfloat16 h2 = __float2bfloat16(vv[2]), h3 = __float2bfloat16(vv[3]);
    H0.x = h0; H0.y = h1; H1.x = h2; H1.y = h3;
    L0.x = __float2bfloat16(vv[0] - __bfloat162float(h0));
    L0.y = __float2bfloat16(vv[1] - __bfloat162float(h1));
    L1.x = __float2bfloat16(vv[2] - __bfloat162float(h2));
    L1.y = __float2bfloat16(vv[3] - __bfloat162float(h3));
    *(__nv_bfloat162*)(g_xh + i) = H0; *(__nv_bfloat162*)(g_xh + i + 2) = H1;
    *(__nv_bfloat162*)(g_xl + i) = L0; *(__nv_bfloat162*)(g_xl + i + 2) = L1;
}
// transpose+split: dst[n][k] = split(src[k][n]); K src rows, N src cols
__device__ __forceinline__ void tsplit_body(const float* src, __nv_bfloat16* dh,
                                            __nv_bfloat16* dl, int K, int N) {
    __shared__ float ts[32][33];
    int k0 = blockIdx.x * 32, n0 = blockIdx.y * 32;
    int tx = threadIdx.x, ty = threadIdx.y;
    #pragma unroll
    for (int i = 0; i < 4; ++i)
        ts[ty + 8 * i][tx] = src[(size_t)(k0 + ty + 8 * i) * N + n0 + tx];
    __syncthreads();
    #pragma unroll
    for (int i = 0; i < 4; ++i) {
        int n = n0 + ty + 8 * i, k = k0 + tx;
        float v = ts[tx][ty + 8 * i];
        __nv_bfloat16 h = __float2bfloat16(v);
        dh[(size_t)n * K + k] = h;
        dl[(size_t)n * K + k] = __float2bfloat16(v - __bfloat162float(h));
    }
}
__global__ void tsplit_w1(const float* __restrict__ klw, const float* __restrict__ mw1) {
    int e = blockIdx.z;
    const float* src = (e < NKAN) ? klw + (size_t)e * DD * HH
                                  : mw1 + (size_t)(e - NKAN) * DD * HH;
    tsplit_body(src, g_w1h + (size_t)e * HH * DD, g_w1l + (size_t)e * HH * DD, DD, HH);
}
__global__ void tsplit_w2m(const float* __restrict__ mw2) {
    int z = blockIdx.z;
    tsplit_body(mw2 + (size_t)z * HH * DD,
                g_w2mh + (size_t)z * DD * HH, g_w2ml + (size_t)z * DD * HH, HH, DD);
}
__global__ void tsplit_w2k(const float* __restrict__ kpw) {
    int z = blockIdx.z, e = z / 3, p = z % 3 + 1;
    tsplit_body(kpw + (size_t)(e * 4 + p) * HH * DD,
                g_w2kh + (size_t)z * DD * HH, g_w2kl + (size_t)z * DD * HH, HH, DD);
}

// ---------------- main fused kernel ----------------
__global__ void __launch_bounds__(256, 1)
ffn_mma(const float* __restrict__ mlp_b1, const float* __restrict__ mlp_b2,
        float* __restrict__ out) {
    extern __shared__ __align__(16) char smc[];
    const uint32_t sb = smem_u32(smc);
    const int tid = threadIdx.x, wid = tid >> 5, lane = tid & 31;
    const int e = blockIdx.y, tile = blockIdx.x, t0 = tile * MT;
    const bool isKan = (e < NKAN);
    const int m = e - NKAN;
    const int npoly = isKan ? 3 : 1;
    const int ns = 2 * npoly;
    const int wm = wid & 1, wn = wid >> 1;

    // initial stages: X | W1[0] | W2 stage0 | W2 stage1
    {
        size_t xoff = (size_t)t0 * DMODEL + e * DD;
        stage64(sb + SM_XH, g_xh + xoff, DMODEL * 2, tid);
        stage64(sb + SM_XL, g_xl + xoff, DMODEL * 2, tid);
        CP_COMMIT();
        size_t w1off = (size_t)e * HH * DD;   // j = 0
        stage64(sb + SM_W1H, g_w1h + w1off, DD * 2, tid);
        stage64(sb + SM_W1L, g_w1l + w1off, DD * 2, tid);
        CP_COMMIT();
        stage_w2(sb, 0, 0, isKan, e, m, tid); CP_COMMIT();
        stage_w2(sb, 0, 1, isKan, e, m, tid); CP_COMMIT();
    }

    float acc[2][2][4][4];   // [half][m16][n8][4]
    #pragma unroll
    for (int a = 0; a < 2; ++a)
        #pragma unroll
        for (int b = 0; b < 2; ++b)
            #pragma unroll
            for (int c = 0; c < 4; ++c)
                #pragma unroll
                for (int d = 0; d < 4; ++d) acc[a][b][c][d] = 0.f;

    const int lr = (lane & 7) + 8 * ((lane >> 3) & 1);
    const int lk = (lane >> 4) * 16;   // byte offset of k8 sub-tile
    const uint32_t aX  = sb + SM_XH  + (32 * wm + lr) * PX  + lk;
    const uint32_t aW1 = sb + SM_W1H + (16 * wn + lr) * PX  + lk;
    const uint32_t aA  = sb + SM_AH  + (32 * wm + lr) * PW2 + lk;
    const uint32_t aW2 = sb + SM_W2H + (32 * wn + lr) * PW2 + lk;

    for (int j = 0; j < 16; ++j) {
        if (isKan && j) { CP_WAIT(6); } else { CP_WAIT(2); }
        __syncthreads();

        // ---- GEMM1: c1[64x64 chunk], warp tile 32x16 ----
        float c1[2][2][4];
        #pragma unroll
        for (int a = 0; a < 2; ++a)
            #pragma unroll
            for (int b = 0; b < 2; ++b)
                #pragma unroll
                for (int c = 0; c < 4; ++c) c1[a][b][c] = 0.f;

        #pragma unroll 4
        for (int kk = 0; kk < 16; ++kk) {
            uint32_t ah0[4], ah1[4], al0[4], al1[4], bh[4], bl[4];
            ldsm4(aX + kk * 32, ah0);
            ldsm4(aX + 16 * PX + kk * 32, ah1);
            ldsm4(aX + DXL + kk * 32, al0);
            ldsm4(aX + DXL + 16 * PX + kk * 32, al1);
            ldsm4(aW1 + kk * 32, bh);
            ldsm4(aW1 + DW1L + kk * 32, bl);
            #pragma unroll
            for (int nt = 0; nt < 2; ++nt) {
                mma16816(c1[0][nt], ah0, bh[nt], bh[nt + 2]);
                mma16816(c1[1][nt], ah1, bh[nt], bh[nt + 2]);
                mma16816(c1[0][nt], al0, bh[nt], bh[nt + 2]);
                mma16816(c1[1][nt], al1, bh[nt], bh[nt + 2]);
                mma16816(c1[0][nt], ah0, bl[nt], bl[nt + 2]);
                mma16816(c1[1][nt], ah1, bl[nt], bl[nt + 2]);
            }
        }
        __syncthreads();
        if (j < 15) {   // prefetch W1[j+1]
            size_t w1off = ((size_t)e * HH + (j + 1) * 64) * DD;
            stage64(sb + SM_W1H, g_w1h + w1off, DD * 2, tid);
            stage64(sb + SM_W1L, g_w1l + w1off, DD * 2, tid);
            CP_COMMIT();
        }

        // ---- activation base values ----
        float tv[2][2][4];
        if (isKan) {
            #pragma unroll
            for (int a = 0; a < 2; ++a)
                #pragma unroll
                for (int b = 0; b < 2; ++b)
                    #pragma unroll
                    for (int c = 0; c < 4; ++c) tv[a][b][c] = tanhf(c1[a][b][c]);
        } else {
            #pragma unroll
            for (int nt = 0; nt < 2; ++nt) {
                int col = j * 64 + 16 * wn + 8 * nt + 2 * (lane & 3);
                float2 bv = *(const float2*)(mlp_b1 + (size_t)m * HH + col);
                #pragma unroll
                for (int a = 0; a < 2; ++a) {
                    tv[a][nt][0] = gelu_tanh(c1[a][nt][0] + bv.x);
                    tv[a][nt][1] = gelu_tanh(c1[a][nt][1] + bv.y);
                    tv[a][nt][2] = gelu_tanh(c1[a][nt][2] + bv.x);
                    tv[a][nt][3] = gelu_tanh(c1[a][nt][3] + bv.y);
                }
            }
        }

        for (int p = 1; p <= npoly; ++p) {
            // write act (hi/lo) for poly p
            #pragma unroll
            for (int a = 0; a < 2; ++a)
                #pragma unroll
                for (int nt = 0; nt < 2; ++nt) {
                    float v[4];
                    #pragma unroll
                    for (int c = 0; c < 4; ++c) {
                        float t = tv[a][nt][c];
                        v[c] = (p == 1) ? t
                             : (p == 2) ? fmaf(2.f * t, t, -1.f)
                                        : t * fmaf(4.f * t, t, -3.f);
                    }
                    int rowb = 32 * wm + 16 * a + (lane >> 2);
                    int colb = (16 * wn + 8 * nt + 2 * (lane & 3)) * 2;
                    uint32_t h01, l01, h23, l23;
                    packhl(v[0], v[1], h01, l01);
                    packhl(v[2], v[3], h23, l23);
                    *(uint32_t*)(smc + SM_AH + rowb * PW2 + colb) = h01;
                    *(uint32_t*)(smc + SM_AL + rowb * PW2 + colb) = l01;
                    *(uint32_t*)(smc + SM_AH + (rowb + 8) * PW2 + colb) = h23;
                    *(uint32_t*)(smc + SM_AL + (rowb + 8) * PW2 + colb) = l23;
                }

            #pragma unroll
            for (int sub = 0; sub < 2; ++sub) {
                int s = (p - 1) * 2 + sub;
                if (s < 2) { CP_WAIT(2); } else { CP_WAIT(1); }
                __syncthreads();
                uint32_t w2b = aW2 + sub * 18432;
                #pragma unroll
                for (int kk = 0; kk < 4; ++kk) {
                    uint32_t Ah0[4], Ah1[4], Al0[4], Al1[4], Bh[8], Bl[8];
                    ldsm4(aA + kk * 32, Ah0);
                    ldsm4(aA + 16 * PW2 + kk * 32, Ah1);
                    ldsm4(aA + DAL + kk * 32, Al0);
                    ldsm4(aA + DAL + 16 * PW2 + kk * 32, Al1);
                    ldsm4(w2b + kk * 32, Bh);
                    ldsm4(w2b + 16 * PW2 + kk * 32, Bh + 4);
                    ldsm4(w2b + DW2L + kk * 32, Bl);
                    ldsm4(w2b + DW2L + 16 * PW2 + kk * 32, Bl + 4);
                    #pragma unroll
                    for (int nt = 0; nt < 4; ++nt) {
                        uint32_t b0h = Bh[4 * (nt >> 1) + (nt & 1)];
                        uint32_t b1h = Bh[4 * (nt >> 1) + (nt & 1) + 2];
                        uint32_t b0l = Bl[4 * (nt >> 1) + (nt & 1)];
                        uint32_t b1l = Bl[4 * (nt >> 1) + (nt & 1) + 2];
                        mma16816(acc[sub][0][nt], Ah0, b0h, b1h);
                        mma16816(acc[sub][1][nt], Ah1, b0h, b1h);
                        mma16816(acc[sub][0][nt], Al0, b0h, b1h);
                        mma16816(acc[sub][1][nt], Al1, b0h, b1h);
                        mma16816(acc[sub][0][nt], Ah0, b0l, b1l);
                        mma16816(acc[sub][1][nt], Ah1, b0l, b1l);
                    }
                }
                __syncthreads();
                int ss = s + 2;
                if (ss < ns) { stage_w2(sb, j, ss, isKan, e, m, tid); CP_COMMIT(); }
                else if (j < 15) { stage_w2(sb, j + 1, ss - ns, isKan, e, m, tid); CP_COMMIT(); }
            }
        }
    }

    // ---- epilogue: out = acc + bias ----
    const float* bp = isKan ? (g_c0 + e * DD) : (mlp_b2 + (size_t)m * DD);
    #pragma unroll
    for (int sub = 0; sub < 2; ++sub)
        #pragma unroll
        for (int a = 0; a < 2; ++a)
            #pragma unroll
            for (int nt = 0; nt < 4; ++nt) {
                int row = t0 + 32 * wm + 16 * a + (lane >> 2);
                int col = sub * 128 + 32 * wn + 8 * nt + 2 * (lane & 3);
                float2 v0, v1;
                v0.x = acc[sub][a][nt][0] + bp[col];
                v0.y = acc[sub][a][nt][1] + bp[col + 1];
                v1.x = acc[sub][a][nt][2] + bp[col];
                v1.y = acc[sub][a][nt][3] + bp[col + 1];
                *(float2*)(out + (size_t)row * DMODEL + e * DD + col) = v0;
                *(float2*)(out + (size_t)(row + 8) * DMODEL + e * DD + col) = v1;
            }
}

extern "C" void kernel_launch(void* const* d_in, const int* in_sizes, int n_in,
                              void* d_out, int out_size) {
    const float* x   = (const float*)d_in[0];
    const float* klw = (const float*)d_in[1];
    const float* kpw = (const float*)d_in[2];
    const float* kb  = (const float*)d_in[3];
    const float* w1  = (const float*)d_in[4];
    const float* b1  = (const float*)d_in[5];
    const float* w2  = (const float*)d_in[6];
    const float* b2  = (const float*)d_in[7];
    float* out = (float*)d_out;

    cudaFuncSetAttribute(ffn_mma, cudaFuncAttributeMaxDynamicSharedMemorySize, SM_TOTAL);

    c0_kernel<<<NKAN, DD>>>(kpw, kb);
    xsplit<<<TOK * DMODEL / 1024, 256>>>(x);
    tsplit_w1<<<dim3(DD / 32, HH / 32, EEXP), dim3(32, 8)>>>(klw, w1);
    tsplit_w2m<<<dim3(HH / 32, DD / 32, 6), dim3(32, 8)>>>(w2);
    tsplit_w2k<<<dim3(HH / 32, DD / 32, 6), dim3(32, 8)>>>(kpw);
    ffn_mma<<<dim3(TOK / MT, EEXP), 256, SM_TOTAL>>>(b1, b2, out);
}

// round 5
// speedup vs baseline: 2.1650x; 1.0183x over previous
#include <cuda_runtime.h>
#include <cuda_bf16.h>
#include <math.h>
#include <stdint.h>

#define TOK    16384
#define DMODEL 2048
#define EEXP   8
#define NKAN   2
#define DD     256
#define HH     1024
#define MT     64

// ---------------- global scratch (bf16 hi/lo pre-splits) ----------------
__device__ __align__(16) __nv_bfloat16 g_xh[(size_t)TOK * DMODEL];
__device__ __align__(16) __nv_bfloat16 g_xl[(size_t)TOK * DMODEL];
__device__ __align__(16) __nv_bfloat16 g_w1h[(size_t)EEXP * HH * DD];   // [e][h][d]
__device__ __align__(16) __nv_bfloat16 g_w1l[(size_t)EEXP * HH * DD];
__device__ __align__(16) __nv_bfloat16 g_w2mh[(size_t)6 * DD * HH];     // [m][o][h]
__device__ __align__(16) __nv_bfloat16 g_w2ml[(size_t)6 * DD * HH];
__device__ __align__(16) __nv_bfloat16 g_w2kh[(size_t)6 * DD * HH];     // [e*3+p-1][o][h]
__device__ __align__(16) __nv_bfloat16 g_w2kl[(size_t)6 * DD * HH];
__device__ float g_c0[NKAN * DD];

// ---------------- smem layout (bytes) ----------------
#define PX     528
#define PW2    144
#define SM_XH  0
#define SM_XL  33792
#define SM_W1H 67584
#define SM_W1L 101376
#define SM_W2H 135168
#define SM_W2L 172032
#define SM_AH  208896
#define SM_AL  218112
#define SM_TOTAL 227328
#define DXL   33792
#define DW1L  33792
#define DW2L  36864
#define DAL   9216

// ---------------- PTX helpers ----------------
__device__ __forceinline__ uint32_t smem_u32(const void* p) {
    uint32_t a;
    asm("{ .reg .u64 t; cvta.to.shared.u64 t, %1; cvt.u32.u64 %0, t; }" : "=r"(a) : "l"(p));
    return a;
}
__device__ __forceinline__ void cp16(uint32_t d, const void* s) {
    asm volatile("cp.async.cg.shared.global [%0], [%1], 16;" :: "r"(d), "l"(s));
}
#define CP_COMMIT() asm volatile("cp.async.commit_group;" ::: "memory")
#define CP_WAIT(N)  asm volatile("cp.async.wait_group %0;" :: "n"(N) : "memory")

__device__ __forceinline__ void ldsm4(uint32_t addr, uint32_t* r) {
    asm volatile("ldmatrix.sync.aligned.m8n8.x4.shared.b16 {%0,%1,%2,%3}, [%4];"
                 : "=r"(r[0]), "=r"(r[1]), "=r"(r[2]), "=r"(r[3]) : "r"(addr));
}
__device__ __forceinline__ void mma16816(float c[4], const uint32_t a[4],
                                         uint32_t b0, uint32_t b1) {
    asm volatile("mma.sync.aligned.m16n8k16.row.col.f32.bf16.bf16.f32 "
                 "{%0,%1,%2,%3}, {%4,%5,%6,%7}, {%8,%9}, {%0,%1,%2,%3};"
                 : "+f"(c[0]), "+f"(c[1]), "+f"(c[2]), "+f"(c[3])
                 : "r"(a[0]), "r"(a[1]), "r"(a[2]), "r"(a[3]), "r"(b0), "r"(b1));
}

__device__ __forceinline__ void packhl(float a, float b, uint32_t& h, uint32_t& l) {
    __nv_bfloat16 ha = __float2bfloat16(a), hb = __float2bfloat16(b);
    float la = a - __bfloat162float(ha), lb = b - __bfloat162float(hb);
    __nv_bfloat162 H, L;
    H.x = ha; H.y = hb;
    L.x = __float2bfloat16(la); L.y = __float2bfloat16(lb);
    h = *reinterpret_cast<uint32_t*>(&H);
    l = *reinterpret_cast<uint32_t*>(&L);
}
__device__ __forceinline__ float fast_tanh(float x) {
    float e = __expf(2.0f * x);
    return 1.0f - __fdividef(2.0f, e + 1.0f);
}
__device__ __forceinline__ float gelu_tanh(float v) {
    float u = 0.7978845608028654f * (v + 0.044715f * v * v * v);
    return 0.5f * v * (1.0f + fast_tanh(u));
}

// ---------------- staging (cp.async) ----------------
__device__ __forceinline__ void stage64(uint32_t dst, const __nv_bfloat16* src,
                                        int spitch, int tid) {
    const char* s = (const char*)src;
    #pragma unroll
    for (int i = 0; i < 8; ++i) {
        int idx = i * 256 + tid, r = idx >> 5, c = idx & 31;
        cp16(dst + r * PX + c * 16, s + (size_t)r * spitch + c * 16);
    }
}
__device__ __forceinline__ void stage128(uint32_t dst, const __nv_bfloat16* src, int tid) {
    const char* s = (const char*)src;
    #pragma unroll
    for (int i = 0; i < 4; ++i) {
        int idx = i * 256 + tid, r = idx >> 3, c = idx & 7;
        cp16(dst + r * PW2 + c * 16, s + (size_t)r * 2048 + c * 16);
    }
}
__device__ __forceinline__ void stage_w2(uint32_t sb, int j, int s, bool isKan,
                                         int e, int m, int tid) {
    int half = s & 1;
    size_t off;
    const __nv_bfloat16 *sh, *sl;
    if (isKan) {
        off = ((size_t)(e * 3 + (s >> 1)) * DD + half * 128) * HH + j * 64;
        sh = g_w2kh + off; sl = g_w2kl + off;
    } else {
        off = ((size_t)m * DD + half * 128) * HH + j * 64;
        sh = g_w2mh + off; sl = g_w2ml + off;
    }
    uint32_t d = sb + SM_W2H + half * 18432;
    stage128(d, sh, tid);
    stage128(d + DW2L, sl, tid);
}

// ---------------- prologue kernels ----------------
__global__ void c0_kernel(const float* __restrict__ kpw, const float* __restrict__ kb) {
    int e = blockIdx.x, o = threadIdx.x;
    const float* w0 = kpw + (size_t)e * 4 * HH * DD;
    float s = kb[e * DD + o];
    for (int h = 0; h < HH; ++h) s += w0[(size_t)h * DD + o];
    g_c0[e * DD + o] = s;
}
__global__ void xsplit(const float* __restrict__ x) {
    size_t i = ((size_t)blockIdx.x * 256 + threadIdx.x) * 4;
    float4 v = *(const float4*)(x + i);
    float vv[4] = {v.x, v.y, v.z, v.w};
    __nv_bfloat162 H0, H1, L0, L1;
    __nv_bfloat16 h0 = __float2bfloat16(vv[0]), h1 = __float2bfloat16(vv[1]);
    __nv_bfloat16 h2 = __float2bfloat16(vv[2]), h3 = __float2bfloat16(vv[3]);
    H0.x = h0; H0.y = h1; H1.x = h2; H1.y = h3;
    L0.x = __float2bfloat16(vv[0] - __bfloat162float(h0));
    L0.y = __float2bfloat16(vv[1] - __bfloat162float(h1));
    L1.x = __float2bfloat16(vv[2] - __bfloat162float(h2));
    L1.y = __float2bfloat16(vv[3] - __bfloat162float(h3));
    *(__nv_bfloat162*)(g_xh + i) = H0; *(__nv_bfloat162*)(g_xh + i + 2) = H1;
    *(__nv_bfloat162*)(g_xl + i) = L0; *(__nv_bfloat162*)(g_xl + i + 2) = L1;
}
__device__ __forceinline__ void tsplit_body(const float* src, __nv_bfloat16* dh,
                                            __nv_bfloat16* dl, int K, int N) {
    __shared__ float ts[32][33];
    int k0 = blockIdx.x * 32, n0 = blockIdx.y * 32;
    int tx = threadIdx.x, ty = threadIdx.y;
    #pragma unroll
    for (int i = 0; i < 4; ++i)
        ts[ty + 8 * i][tx] = src[(size_t)(k0 + ty + 8 * i) * N + n0 + tx];
    __syncthreads();
    #pragma unroll
    for (int i = 0; i < 4; ++i) {
        int n = n0 + ty + 8 * i, k = k0 + tx;
        float v = ts[tx][ty + 8 * i];
        __nv_bfloat16 h = __float2bfloat16(v);
        dh[(size_t)n * K + k] = h;
        dl[(size_t)n * K + k] = __float2bfloat16(v - __bfloat162float(h));
    }
}
__global__ void tsplit_w1(const float* __restrict__ klw, const float* __restrict__ mw1) {
    int e = blockIdx.z;
    const float* src = (e < NKAN) ? klw + (size_t)e * DD * HH
                                  : mw1 + (size_t)(e - NKAN) * DD * HH;
    tsplit_body(src, g_w1h + (size_t)e * HH * DD, g_w1l + (size_t)e * HH * DD, DD, HH);
}
__global__ void tsplit_w2m(const float* __restrict__ mw2) {
    int z = blockIdx.z;
    tsplit_body(mw2 + (size_t)z * HH * DD,
                g_w2mh + (size_t)z * DD * HH, g_w2ml + (size_t)z * DD * HH, HH, DD);
}
__global__ void tsplit_w2k(const float* __restrict__ kpw) {
    int z = blockIdx.z, e = z / 3, p = z % 3 + 1;
    tsplit_body(kpw + (size_t)(e * 4 + p) * HH * DD,
                g_w2kh + (size_t)z * DD * HH, g_w2kl + (size_t)z * DD * HH, HH, DD);
}

// ---------------- main fused kernel ----------------
__global__ void __launch_bounds__(256, 1)
ffn_mma(const float* __restrict__ mlp_b1, const float* __restrict__ mlp_b2,
        float* __restrict__ out) {
    extern __shared__ __align__(16) char smc[];
    const uint32_t sb = smem_u32(smc);
    const int tid = threadIdx.x, wid = tid >> 5, lane = tid & 31;
    const int e = blockIdx.y, tile = blockIdx.x, t0 = tile * MT;
    const bool isKan = (e < NKAN);
    const int m = e - NKAN;
    const int npoly = isKan ? 3 : 1;
    const int ns = 2 * npoly;
    const int wm = wid & 1, wn = wid >> 1;

    {
        size_t xoff = (size_t)t0 * DMODEL + e * DD;
        stage64(sb + SM_XH, g_xh + xoff, DMODEL * 2, tid);
        stage64(sb + SM_XL, g_xl + xoff, DMODEL * 2, tid);
        CP_COMMIT();
        size_t w1off = (size_t)e * HH * DD;
        stage64(sb + SM_W1H, g_w1h + w1off, DD * 2, tid);
        stage64(sb + SM_W1L, g_w1l + w1off, DD * 2, tid);
        CP_COMMIT();
        stage_w2(sb, 0, 0, isKan, e, m, tid); CP_COMMIT();
        stage_w2(sb, 0, 1, isKan, e, m, tid); CP_COMMIT();
    }

    float acc[2][2][4][4];
    #pragma unroll
    for (int a = 0; a < 2; ++a)
        #pragma unroll
        for (int b = 0; b < 2; ++b)
            #pragma unroll
            for (int c = 0; c < 4; ++c)
                #pragma unroll
                for (int d = 0; d < 4; ++d) acc[a][b][c][d] = 0.f;

    const int lr = (lane & 7) + 8 * ((lane >> 3) & 1);
    const int lk = (lane >> 4) * 16;
    const uint32_t aX  = sb + SM_XH  + (32 * wm + lr) * PX  + lk;
    const uint32_t aW1 = sb + SM_W1H + (16 * wn + lr) * PX  + lk;
    const uint32_t aA  = sb + SM_AH  + (32 * wm + lr) * PW2 + lk;
    const uint32_t aW2 = sb + SM_W2H + (32 * wn + lr) * PW2 + lk;

    for (int j = 0; j < 16; ++j) {
        if (isKan && j) { CP_WAIT(6); } else { CP_WAIT(2); }
        __syncthreads();

        // ---- GEMM1: 2-stage ldsm pipeline + round-robin acc order ----
        float c1[2][2][4];
        #pragma unroll
        for (int a = 0; a < 2; ++a)
            #pragma unroll
            for (int b = 0; b < 2; ++b)
                #pragma unroll
                for (int c = 0; c < 4; ++c) c1[a][b][c] = 0.f;

        uint32_t fa[2][16], fb[2][8];
        #define LD1(kk, bi) do { \
            ldsm4(aX + (kk) * 32, &fa[bi][0]); \
            ldsm4(aX + 16 * PX + (kk) * 32, &fa[bi][4]); \
            ldsm4(aX + DXL + (kk) * 32, &fa[bi][8]); \
            ldsm4(aX + DXL + 16 * PX + (kk) * 32, &fa[bi][12]); \
            ldsm4(aW1 + (kk) * 32, &fb[bi][0]); \
            ldsm4(aW1 + DW1L + (kk) * 32, &fb[bi][4]); \
        } while (0)
        LD1(0, 0);
        #pragma unroll
        for (int kk = 0; kk < 16; ++kk) {
            const int cur = kk & 1;
            if (kk < 15) LD1(kk + 1, cur ^ 1);
            const uint32_t* A = fa[cur];
            const uint32_t* B = fb[cur];
            // term hh
            mma16816(c1[0][0], A + 0, B[0], B[2]);
            mma16816(c1[0][1], A + 0, B[1], B[3]);
            mma16816(c1[1][0], A + 4, B[0], B[2]);
            mma16816(c1[1][1], A + 4, B[1], B[3]);
            // term lh
            mma16816(c1[0][0], A + 8,  B[0], B[2]);
            mma16816(c1[0][1], A + 8,  B[1], B[3]);
            mma16816(c1[1][0], A + 12, B[0], B[2]);
            mma16816(c1[1][1], A + 12, B[1], B[3]);
            // term hl
            mma16816(c1[0][0], A + 0, B[4], B[6]);
            mma16816(c1[0][1], A + 0, B[5], B[7]);
            mma16816(c1[1][0], A + 4, B[4], B[6]);
            mma16816(c1[1][1], A + 4, B[5], B[7]);
        }
        #undef LD1
        __syncthreads();
        if (j < 15) {
            size_t w1off = ((size_t)e * HH + (j + 1) * 64) * DD;
            stage64(sb + SM_W1H, g_w1h + w1off, DD * 2, tid);
            stage64(sb + SM_W1L, g_w1l + w1off, DD * 2, tid);
            CP_COMMIT();
        }

        // ---- activation base values ----
        float tv[2][2][4];
        if (isKan) {
            #pragma unroll
            for (int a = 0; a < 2; ++a)
                #pragma unroll
                for (int b = 0; b < 2; ++b)
                    #pragma unroll
                    for (int c = 0; c < 4; ++c) tv[a][b][c] = fast_tanh(c1[a][b][c]);
        } else {
            #pragma unroll
            for (int nt = 0; nt < 2; ++nt) {
                int col = j * 64 + 16 * wn + 8 * nt + 2 * (lane & 3);
                float2 bv = *(const float2*)(mlp_b1 + (size_t)m * HH + col);
                #pragma unroll
                for (int a = 0; a < 2; ++a) {
                    tv[a][nt][0] = gelu_tanh(c1[a][nt][0] + bv.x);
                    tv[a][nt][1] = gelu_tanh(c1[a][nt][1] + bv.y);
                    tv[a][nt][2] = gelu_tanh(c1[a][nt][2] + bv.x);
                    tv[a][nt][3] = gelu_tanh(c1[a][nt][3] + bv.y);
                }
            }
        }

        for (int p = 1; p <= npoly; ++p) {
            #pragma unroll
            for (int a = 0; a < 2; ++a)
                #pragma unroll
                for (int nt = 0; nt < 2; ++nt) {
                    float v[4];
                    #pragma unroll
                    for (int c = 0; c < 4; ++c) {
                        float t = tv[a][nt][c];
                        v[c] = (p == 1) ? t
                             : (p == 2) ? fmaf(2.f * t, t, -1.f)
                                        : t * fmaf(4.f * t, t, -3.f);
                    }
                    int rowb = 32 * wm + 16 * a + (lane >> 2);
                    int colb = (16 * wn + 8 * nt + 2 * (lane & 3)) * 2;
                    uint32_t h01, l01, h23, l23;
                    packhl(v[0], v[1], h01, l01);
                    packhl(v[2], v[3], h23, l23);
                    *(uint32_t*)(smc + SM_AH + rowb * PW2 + colb) = h01;
                    *(uint32_t*)(smc + SM_AL + rowb * PW2 + colb) = l01;
                    *(uint32_t*)(smc + SM_AH + (rowb + 8) * PW2 + colb) = h23;
                    *(uint32_t*)(smc + SM_AL + (rowb + 8) * PW2 + colb) = l23;
                }

            #pragma unroll
            for (int sub = 0; sub < 2; ++sub) {
                int s = (p - 1) * 2 + sub;
                if (s < 2) { CP_WAIT(2); } else { CP_WAIT(1); }
                __syncthreads();
                const uint32_t w2b = aW2 + sub * 18432;
                uint32_t Fa[2][16], Fb[2][16];
                #define LD2(kk, bi) do { \
                    ldsm4(aA + (kk) * 32, &Fa[bi][0]); \
                    ldsm4(aA + 16 * PW2 + (kk) * 32, &Fa[bi][4]); \
                    ldsm4(aA + DAL + (kk) * 32, &Fa[bi][8]); \
                    ldsm4(aA + DAL + 16 * PW2 + (kk) * 32, &Fa[bi][12]); \
                    ldsm4(w2b + (kk) * 32, &Fb[bi][0]); \
                    ldsm4(w2b + 16 * PW2 + (kk) * 32, &Fb[bi][4]); \
                    ldsm4(w2b + DW2L + (kk) * 32, &Fb[bi][8]); \
                    ldsm4(w2b + DW2L + 16 * PW2 + (kk) * 32, &Fb[bi][12]); \
                } while (0)
                LD2(0, 0);
                #pragma unroll
                for (int kk = 0; kk < 4; ++kk) {
                    const int cur = kk & 1;
                    if (kk < 3) LD2(kk + 1, cur ^ 1);
                    const uint32_t* A = Fa[cur];
                    const uint32_t* B = Fb[cur];
                    // term hh: 8-tile round robin
                    #pragma unroll
                    for (int a = 0; a < 2; ++a)
                        #pragma unroll
                        for (int nt = 0; nt < 4; ++nt)
                            mma16816(acc[sub][a][nt], A + a * 4,
                                     B[4 * (nt >> 1) + (nt & 1)],
                                     B[4 * (nt >> 1) + (nt & 1) + 2]);
                    // term lh
                    #pragma unroll
                    for (int a = 0; a < 2; ++a)
                        #pragma unroll
                        for (int nt = 0; nt < 4; ++nt)
                            mma16816(acc[sub][a][nt], A + 8 + a * 4,
                                     B[4 * (nt >> 1) + (nt & 1)],
                                     B[4 * (nt >> 1) + (nt & 1) + 2]);
                    // term hl
                    #pragma unroll
                    for (int a = 0; a < 2; ++a)
                        #pragma unroll
                        for (int nt = 0; nt < 4; ++nt)
                            mma16816(acc[sub][a][nt], A + a * 4,
                                     B[8 + 4 * (nt >> 1) + (nt & 1)],
                                     B[8 + 4 * (nt >> 1) + (nt & 1) + 2]);
                }
                #undef LD2
                __syncthreads();
                int ss = s + 2;
                if (ss < ns) { stage_w2(sb, j, ss, isKan, e, m, tid); CP_COMMIT(); }
                else if (j < 15) { stage_w2(sb, j + 1, ss - ns, isKan, e, m, tid); CP_COMMIT(); }
            }
        }
    }

    // ---- epilogue: out = acc + bias ----
    const float* bp = isKan ? (g_c0 + e * DD) : (mlp_b2 + (size_t)m * DD);
    #pragma unroll
    for (int sub = 0; sub < 2; ++sub)
        #pragma unroll
        for (int a = 0; a < 2; ++a)
            #pragma unroll
            for (int nt = 0; nt < 4; ++nt) {
                int row = t0 + 32 * wm + 16 * a + (lane >> 2);
                int col = sub * 128 + 32 * wn + 8 * nt + 2 * (lane & 3);
                float2 v0, v1;
                v0.x = acc[sub][a][nt][0] + bp[col];
                v0.y = acc[sub][a][nt][1] + bp[col + 1];
                v1.x = acc[sub][a][nt][2] + bp[col];
                v1.y = acc[sub][a][nt][3] + bp[col + 1];
                *(float2*)(out + (size_t)row * DMODEL + e * DD + col) = v0;
                *(float2*)(out + (size_t)(row + 8) * DMODEL + e * DD + col) = v1;
            }
}

extern "C" void kernel_launch(void* const* d_in, const int* in_sizes, int n_in,
                              void* d_out, int out_size) {
    const float* x   = (const float*)d_in[0];
    const float* klw = (const float*)d_in[1];
    const float* kpw = (const float*)d_in[2];
    const float* kb  = (const float*)d_in[3];
    const float* w1  = (const float*)d_in[4];
    const float* b1  = (const float*)d_in[5];
    const float* w2  = (const float*)d_in[6];
    const float* b2  = (const float*)d_in[7];
    float* out = (float*)d_out;

    cudaFuncSetAttribute(ffn_mma, cudaFuncAttributeMaxDynamicSharedMemorySize, SM_TOTAL);

    c0_kernel<<<NKAN, DD>>>(kpw, kb);
    xsplit<<<TOK * DMODEL / 1024, 256>>>(x);
    tsplit_w1<<<dim3(DD / 32, HH / 32, EEXP), dim3(32, 8)>>>(klw, w1);
    tsplit_w2m<<<dim3(HH / 32, DD / 32, 6), dim3(32, 8)>>>(w2);
    tsplit_w2k<<<dim3(HH / 32, DD / 32, 6), dim3(32, 8)>>>(kpw);
    ffn_mma<<<dim3(TOK / MT, EEXP), 256, SM_TOTAL>>>(b1, b2, out);
}

// round 6
// speedup vs baseline: 2.8624x; 1.3221x over previous
#include <cuda_runtime.h>
#include <cuda_fp16.h>
#include <math.h>
#include <stdint.h>

#define TOK    16384
#define DMODEL 2048
#define EEXP   8
#define NKAN   2
#define DD     256
#define HH     1024
#define MT     64
#define WSC    64.0f
#define WSCI   (1.0f / 64.0f)

// ---------------- global scratch (fp16; weights pre-scaled x64, hi/lo split) ----
__device__ __align__(16) __half g_x[(size_t)TOK * DMODEL];
__device__ __align__(16) __half g_w1h[(size_t)EEXP * HH * DD];   // [e][h][d]
__device__ __align__(16) __half g_w1l[(size_t)EEXP * HH * DD];
__device__ __align__(16) __half g_w2mh[(size_t)6 * DD * HH];     // [m][o][h]
__device__ __align__(16) __half g_w2ml[(size_t)6 * DD * HH];
__device__ __align__(16) __half g_w2kh[(size_t)6 * DD * HH];     // [e*3+p-1][o][h]
__device__ __align__(16) __half g_w2kl[(size_t)6 * DD * HH];
__device__ float g_c0[NKAN * DD];

// ---------------- smem layout (bytes) ----------------
#define PX     528
#define PW2    144
#define SM_X   0                      // 64 x 528 = 33792
#define SM_W1H 33792                  // 64 x 528
#define SM_W1L 67584
#define SM_W2H 101376                 // 2 halves x 128 x 144 = 36864
#define SM_W2L 138240
#define SM_A   175104                 // 64 x 144 = 9216
#define SM_TOTAL 184320
#define DW1L  33792
#define DW2L  36864

// ---------------- PTX helpers ----------------
__device__ __forceinline__ uint32_t smem_u32(const void* p) {
    uint32_t a;
    asm("{ .reg .u64 t; cvta.to.shared.u64 t, %1; cvt.u32.u64 %0, t; }" : "=r"(a) : "l"(p));
    return a;
}
__device__ __forceinline__ void cp16(uint32_t d, const void* s) {
    asm volatile("cp.async.cg.shared.global [%0], [%1], 16;" :: "r"(d), "l"(s));
}
#define CP_COMMIT() asm volatile("cp.async.commit_group;" ::: "memory")
#define CP_WAIT(N)  asm volatile("cp.async.wait_group %0;" :: "n"(N) : "memory")

__device__ __forceinline__ void ldsm4(uint32_t addr, uint32_t* r) {
    asm volatile("ldmatrix.sync.aligned.m8n8.x4.shared.b16 {%0,%1,%2,%3}, [%4];"
                 : "=r"(r[0]), "=r"(r[1]), "=r"(r[2]), "=r"(r[3]) : "r"(addr));
}
__device__ __forceinline__ void mma16816(float c[4], const uint32_t a[4],
                                         uint32_t b0, uint32_t b1) {
    asm volatile("mma.sync.aligned.m16n8k16.row.col.f32.f16.f16.f32 "
                 "{%0,%1,%2,%3}, {%4,%5,%6,%7}, {%8,%9}, {%0,%1,%2,%3};"
                 : "+f"(c[0]), "+f"(c[1]), "+f"(c[2]), "+f"(c[3])
                 : "r"(a[0]), "r"(a[1]), "r"(a[2]), "r"(a[3]), "r"(b0), "r"(b1));
}
__device__ __forceinline__ float fast_tanh(float x) {
    float e = __expf(2.0f * x);
    return 1.0f - __fdividef(2.0f, e + 1.0f);
}
__device__ __forceinline__ float gelu_tanh(float v) {
    float u = 0.7978845608028654f * (v + 0.044715f * v * v * v);
    return 0.5f * v * (1.0f + fast_tanh(u));
}

// ---------------- staging (cp.async) ----------------
__device__ __forceinline__ void stage64(uint32_t dst, const __half* src,
                                        int spitch, int tid) {
    const char* s = (const char*)src;
    #pragma unroll
    for (int i = 0; i < 8; ++i) {
        int idx = i * 256 + tid, r = idx >> 5, c = idx & 31;
        cp16(dst + r * PX + c * 16, s + (size_t)r * spitch + c * 16);
    }
}
__device__ __forceinline__ void stage128(uint32_t dst, const __half* src, int tid) {
    const char* s = (const char*)src;   // src pitch = HH*2 = 2048 B
    #pragma unroll
    for (int i = 0; i < 4; ++i) {
        int idx = i * 256 + tid, r = idx >> 3, c = idx & 7;
        cp16(dst + r * PW2 + c * 16, s + (size_t)r * 2048 + c * 16);
    }
}
__device__ __forceinline__ void stage_w2(uint32_t sb, int j, int s, bool isKan,
                                         int e, int m, int tid) {
    int half = s & 1;
    size_t off;
    const __half *sh, *sl;
    if (isKan) {
        off = ((size_t)(e * 3 + (s >> 1)) * DD + half * 128) * HH + j * 64;
        sh = g_w2kh + off; sl = g_w2kl + off;
    } else {
        off = ((size_t)m * DD + half * 128) * HH + j * 64;
        sh = g_w2mh + off; sl = g_w2ml + off;
    }
    uint32_t d = sb + SM_W2H + half * 18432;
    stage128(d, sh, tid);
    stage128(d + DW2L, sl, tid);
}

// ---------------- prologue kernels ----------------
__global__ void c0_kernel(const float* __restrict__ kpw, const float* __restrict__ kb) {
    int e = blockIdx.x, o = threadIdx.x;
    const float* w0 = kpw + (size_t)e * 4 * HH * DD;
    float s = kb[e * DD + o];
    for (int h = 0; h < HH; ++h) s += w0[(size_t)h * DD + o];
    g_c0[e * DD + o] = s;
}
__global__ void xhalf(const float* __restrict__ x) {
    size_t i = ((size_t)blockIdx.x * 256 + threadIdx.x) * 4;
    float4 v = *(const float4*)(x + i);
    __half2 a = __floats2half2_rn(v.x, v.y);
    __half2 b = __floats2half2_rn(v.z, v.w);
    *(__half2*)(g_x + i) = a;
    *(__half2*)(g_x + i + 2) = b;
}
// transpose+split (scaled by WSC): dst[n][k] = split(WSC*src[k][n])
__device__ __forceinline__ void tsplit_body(const float* src, __half* dh,
                                            __half* dl, int K, int N) {
    __shared__ float ts[32][33];
    int k0 = blockIdx.x * 32, n0 = blockIdx.y * 32;
    int tx = threadIdx.x, ty = threadIdx.y;
    #pragma unroll
    for (int i = 0; i < 4; ++i)
        ts[ty + 8 * i][tx] = src[(size_t)(k0 + ty + 8 * i) * N + n0 + tx];
    __syncthreads();
    #pragma unroll
    for (int i = 0; i < 4; ++i) {
        int n = n0 + ty + 8 * i, k = k0 + tx;
        float v = ts[tx][ty + 8 * i] * WSC;
        __half h = __float2half(v);
        dh[(size_t)n * K + k] = h;
        dl[(size_t)n * K + k] = __float2half(v - __half2float(h));
    }
}
__global__ void tsplit_w1(const float* __restrict__ klw, const float* __restrict__ mw1) {
    int e = blockIdx.z;
    const float* src = (e < NKAN) ? klw + (size_t)e * DD * HH
                                  : mw1 + (size_t)(e - NKAN) * DD * HH;
    tsplit_body(src, g_w1h + (size_t)e * HH * DD, g_w1l + (size_t)e * HH * DD, DD, HH);
}
__global__ void tsplit_w2m(const float* __restrict__ mw2) {
    int z = blockIdx.z;
    tsplit_body(mw2 + (size_t)z * HH * DD,
                g_w2mh + (size_t)z * DD * HH, g_w2ml + (size_t)z * DD * HH, HH, DD);
}
__global__ void tsplit_w2k(const float* __restrict__ kpw) {
    int z = blockIdx.z, e = z / 3, p = z % 3 + 1;
    tsplit_body(kpw + (size_t)(e * 4 + p) * HH * DD,
                g_w2kh + (size_t)z * DD * HH, g_w2kl + (size_t)z * DD * HH, HH, DD);
}

// ---------------- main fused kernel ----------------
__global__ void __launch_bounds__(256, 1)
ffn_mma(const float* __restrict__ mlp_b1, const float* __restrict__ mlp_b2,
        float* __restrict__ out) {
    extern __shared__ __align__(16) char smc[];
    const uint32_t sb = smem_u32(smc);
    const int tid = threadIdx.x, wid = tid >> 5, lane = tid & 31;
    const int e = blockIdx.y, tile = blockIdx.x, t0 = tile * MT;
    const bool isKan = (e < NKAN);
    const int m = e - NKAN;
    const int npoly = isKan ? 3 : 1;
    const int ns = 2 * npoly;
    const int wm = wid & 1, wn = wid >> 1;

    {
        size_t xoff = (size_t)t0 * DMODEL + e * DD;
        stage64(sb + SM_X, g_x + xoff, DMODEL * 2, tid);
        CP_COMMIT();
        size_t w1off = (size_t)e * HH * DD;
        stage64(sb + SM_W1H, g_w1h + w1off, DD * 2, tid);
        stage64(sb + SM_W1L, g_w1l + w1off, DD * 2, tid);
        CP_COMMIT();
        stage_w2(sb, 0, 0, isKan, e, m, tid); CP_COMMIT();
        stage_w2(sb, 0, 1, isKan, e, m, tid); CP_COMMIT();
    }

    float acc[2][2][4][4];
    #pragma unroll
    for (int a = 0; a < 2; ++a)
        #pragma unroll
        for (int b = 0; b < 2; ++b)
            #pragma unroll
            for (int c = 0; c < 4; ++c)
                #pragma unroll
                for (int d = 0; d < 4; ++d) acc[a][b][c][d] = 0.f;

    const int lr = (lane & 7) + 8 * ((lane >> 3) & 1);
    const int lk = (lane >> 4) * 16;
    const uint32_t aX  = sb + SM_X   + (32 * wm + lr) * PX  + lk;
    const uint32_t aW1 = sb + SM_W1H + (16 * wn + lr) * PX  + lk;
    const uint32_t aA  = sb + SM_A   + (32 * wm + lr) * PW2 + lk;
    const uint32_t aW2 = sb + SM_W2H + (32 * wn + lr) * PW2 + lk;

    for (int j = 0; j < 16; ++j) {
        if (isKan && j) { CP_WAIT(6); } else { CP_WAIT(2); }
        __syncthreads();

        // ---- GEMM1: A(fp16) x (W1h + W1l), warp tile 32x16 ----
        float c1[2][2][4];
        #pragma unroll
        for (int a = 0; a < 2; ++a)
            #pragma unroll
            for (int b = 0; b < 2; ++b)
                #pragma unroll
                for (int c = 0; c < 4; ++c) c1[a][b][c] = 0.f;

        uint32_t fa[2][8], fb[2][8];
        #define LD1(kk, bi) do { \
            ldsm4(aX + (kk) * 32, &fa[bi][0]); \
            ldsm4(aX + 16 * PX + (kk) * 32, &fa[bi][4]); \
            ldsm4(aW1 + (kk) * 32, &fb[bi][0]); \
            ldsm4(aW1 + DW1L + (kk) * 32, &fb[bi][4]); \
        } while (0)
        LD1(0, 0);
        #pragma unroll
        for (int kk = 0; kk < 16; ++kk) {
            const int cur = kk & 1;
            if (kk < 15) LD1(kk + 1, cur ^ 1);
            const uint32_t* A = fa[cur];
            const uint32_t* B = fb[cur];
            mma16816(c1[0][0], A + 0, B[0], B[2]);
            mma16816(c1[0][1], A + 0, B[1], B[3]);
            mma16816(c1[1][0], A + 4, B[0], B[2]);
            mma16816(c1[1][1], A + 4, B[1], B[3]);
            mma16816(c1[0][0], A + 0, B[4], B[6]);
            mma16816(c1[0][1], A + 0, B[5], B[7]);
            mma16816(c1[1][0], A + 4, B[4], B[6]);
            mma16816(c1[1][1], A + 4, B[5], B[7]);
        }
        #undef LD1
        __syncthreads();
        if (j < 15) {
            size_t w1off = ((size_t)e * HH + (j + 1) * 64) * DD;
            stage64(sb + SM_W1H, g_w1h + w1off, DD * 2, tid);
            stage64(sb + SM_W1L, g_w1l + w1off, DD * 2, tid);
            CP_COMMIT();
        }

        // ---- activation (undo x64 weight scale) ----
        float tv[2][2][4];
        if (isKan) {
            #pragma unroll
            for (int a = 0; a < 2; ++a)
                #pragma unroll
                for (int b = 0; b < 2; ++b)
                    #pragma unroll
                    for (int c = 0; c < 4; ++c)
                        tv[a][b][c] = fast_tanh(c1[a][b][c] * WSCI);
        } else {
            #pragma unroll
            for (int nt = 0; nt < 2; ++nt) {
                int col = j * 64 + 16 * wn + 8 * nt + 2 * (lane & 3);
                float2 bv = *(const float2*)(mlp_b1 + (size_t)m * HH + col);
                #pragma unroll
                for (int a = 0; a < 2; ++a) {
                    tv[a][nt][0] = gelu_tanh(c1[a][nt][0] * WSCI + bv.x);
                    tv[a][nt][1] = gelu_tanh(c1[a][nt][1] * WSCI + bv.y);
                    tv[a][nt][2] = gelu_tanh(c1[a][nt][2] * WSCI + bv.x);
                    tv[a][nt][3] = gelu_tanh(c1[a][nt][3] * WSCI + bv.y);
                }
            }
        }

        for (int p = 1; p <= npoly; ++p) {
            #pragma unroll
            for (int a = 0; a < 2; ++a)
                #pragma unroll
                for (int nt = 0; nt < 2; ++nt) {
                    float v[4];
                    #pragma unroll
                    for (int c = 0; c < 4; ++c) {
                        float t = tv[a][nt][c];
                        v[c] = (p == 1) ? t
                             : (p == 2) ? fmaf(2.f * t, t, -1.f)
                                        : t * fmaf(4.f * t, t, -3.f);
                    }
                    int rowb = 32 * wm + 16 * a + (lane >> 2);
                    int colb = (16 * wn + 8 * nt + 2 * (lane & 3)) * 2;
                    __half2 h01 = __floats2half2_rn(v[0], v[1]);
                    __half2 h23 = __floats2half2_rn(v[2], v[3]);
                    *(__half2*)(smc + SM_A + rowb * PW2 + colb) = h01;
                    *(__half2*)(smc + SM_A + (rowb + 8) * PW2 + colb) = h23;
                }

            #pragma unroll
            for (int sub = 0; sub < 2; ++sub) {
                int s = (p - 1) * 2 + sub;
                if (s < 2) { CP_WAIT(2); } else { CP_WAIT(1); }
                __syncthreads();
                const uint32_t w2b = aW2 + sub * 18432;
                uint32_t Fa[2][8], Fb[2][16];
                #define LD2(kk, bi) do { \
                    ldsm4(aA + (kk) * 32, &Fa[bi][0]); \
                    ldsm4(aA + 16 * PW2 + (kk) * 32, &Fa[bi][4]); \
                    ldsm4(w2b + (kk) * 32, &Fb[bi][0]); \
                    ldsm4(w2b + 16 * PW2 + (kk) * 32, &Fb[bi][4]); \
                    ldsm4(w2b + DW2L + (kk) * 32, &Fb[bi][8]); \
                    ldsm4(w2b + DW2L + 16 * PW2 + (kk) * 32, &Fb[bi][12]); \
                } while (0)
                LD2(0, 0);
                #pragma unroll
                for (int kk = 0; kk < 4; ++kk) {
                    const int cur = kk & 1;
                    if (kk < 3) LD2(kk + 1, cur ^ 1);
                    const uint32_t* A = Fa[cur];
                    const uint32_t* B = Fb[cur];
                    // hi term: 8-tile round robin
                    #pragma unroll
                    for (int a = 0; a < 2; ++a)
                        #pragma unroll
                        for (int nt = 0; nt < 4; ++nt)
                            mma16816(acc[sub][a][nt], A + a * 4,
                                     B[4 * (nt >> 1) + (nt & 1)],
                                     B[4 * (nt >> 1) + (nt & 1) + 2]);
                    // lo term
                    #pragma unroll
                    for (int a = 0; a < 2; ++a)
                        #pragma unroll
                        for (int nt = 0; nt < 4; ++nt)
                            mma16816(acc[sub][a][nt], A + a * 4,
                                     B[8 + 4 * (nt >> 1) + (nt & 1)],
                                     B[8 + 4 * (nt >> 1) + (nt & 1) + 2]);
                }
                #undef LD2
                __syncthreads();
                int ss = s + 2;
                if (ss < ns) { stage_w2(sb, j, ss, isKan, e, m, tid); CP_COMMIT(); }
                else if (j < 15) { stage_w2(sb, j + 1, ss - ns, isKan, e, m, tid); CP_COMMIT(); }
            }
        }
    }

    // ---- epilogue: out = acc/64 + bias ----
    const float* bp = isKan ? (g_c0 + e * DD) : (mlp_b2 + (size_t)m * DD);
    #pragma unroll
    for (int sub = 0; sub < 2; ++sub)
        #pragma unroll
        for (int a = 0; a < 2; ++a)
            #pragma unroll
            for (int nt = 0; nt < 4; ++nt) {
                int row = t0 + 32 * wm + 16 * a + (lane >> 2);
                int col = sub * 128 + 32 * wn + 8 * nt + 2 * (lane & 3);
                float2 v0, v1;
                v0.x = acc[sub][a][nt][0] * WSCI + bp[col];
                v0.y = acc[sub][a][nt][1] * WSCI + bp[col + 1];
                v1.x = acc[sub][a][nt][2] * WSCI + bp[col];
                v1.y = acc[sub][a][nt][3] * WSCI + bp[col + 1];
                *(float2*)(out + (size_t)row * DMODEL + e * DD + col) = v0;
                *(float2*)(out + (size_t)(row + 8) * DMODEL + e * DD + col) = v1;
            }
}

extern "C" void kernel_launch(void* const* d_in, const int* in_sizes, int n_in,
                              void* d_out, int out_size) {
    const float* x   = (const float*)d_in[0];
    const float* klw = (const float*)d_in[1];
    const float* kpw = (const float*)d_in[2];
    const float* kb  = (const float*)d_in[3];
    const float* w1  = (const float*)d_in[4];
    const float* b1  = (const float*)d_in[5];
    const float* w2  = (const float*)d_in[6];
    const float* b2  = (const float*)d_in[7];
    float* out = (float*)d_out;

    cudaFuncSetAttribute(ffn_mma, cudaFuncAttributeMaxDynamicSharedMemorySize, SM_TOTAL);

    c0_kernel<<<NKAN, DD>>>(kpw, kb);
    xhalf<<<TOK * DMODEL / 1024, 256>>>(x);
    tsplit_w1<<<dim3(DD / 32, HH / 32, EEXP), dim3(32, 8)>>>(klw, w1);
    tsplit_w2m<<<dim3(HH / 32, DD / 32, 6), dim3(32, 8)>>>(w2);
    tsplit_w2k<<<dim3(HH / 32, DD / 32, 6), dim3(32, 8)>>>(kpw);
    ffn_mma<<<dim3(TOK / MT, EEXP), 256, SM_TOTAL>>>(b1, b2, out);
}

// round 7
// speedup vs baseline: 3.5469x; 1.2391x over previous
#include <cuda_runtime.h>
#include <cuda_fp16.h>
#include <math.h>
#include <stdint.h>

#define TOK    16384
#define DMODEL 2048
#define EEXP   8
#define NKAN   2
#define DD     256
#define HH     1024
#define MT     128
#define NTHR   512
#define WSC    64.0f
#define WSCI   (1.0f / 64.0f)

// ---------------- global scratch (fp16; weights pre-scaled x64, hi/lo split) ----
__device__ __align__(16) __half g_x[(size_t)TOK * DMODEL];
__device__ __align__(16) __half g_w1h[(size_t)EEXP * HH * DD];   // [e][h][d]
__device__ __align__(16) __half g_w1l[(size_t)EEXP * HH * DD];
__device__ __align__(16) __half g_w2mh[(size_t)6 * DD * HH];     // [m][o][h]
__device__ __align__(16) __half g_w2ml[(size_t)6 * DD * HH];
__device__ __align__(16) __half g_w2kh[(size_t)6 * DD * HH];     // [e*3+p-1][o][h]
__device__ __align__(16) __half g_w2kl[(size_t)6 * DD * HH];
__device__ float g_c0[NKAN * DD];

// ---------------- smem layout (bytes) ----------------
#define PX     528
#define PW2    144
#define SM_X   0                      // 128 x 528 = 67584
#define SM_W1H 67584                  // 64 x 528 = 33792
#define SM_W1L 101376
#define SM_W2H 135168                 // 2 halves x 128 x 144 = 36864
#define SM_W2L 172032
#define SM_A   208896                 // 128 x 144 = 18432
#define SM_TOTAL 227328
#define DW1L  33792
#define DW2L  36864

// ---------------- PTX helpers ----------------
__device__ __forceinline__ uint32_t smem_u32(const void* p) {
    uint32_t a;
    asm("{ .reg .u64 t; cvta.to.shared.u64 t, %1; cvt.u32.u64 %0, t; }" : "=r"(a) : "l"(p));
    return a;
}
__device__ __forceinline__ void cp16(uint32_t d, const void* s) {
    asm volatile("cp.async.cg.shared.global [%0], [%1], 16;" :: "r"(d), "l"(s));
}
#define CP_COMMIT() asm volatile("cp.async.commit_group;" ::: "memory")
#define CP_WAIT(N)  asm volatile("cp.async.wait_group %0;" :: "n"(N) : "memory")

__device__ __forceinline__ void ldsm4(uint32_t addr, uint32_t* r) {
    asm volatile("ldmatrix.sync.aligned.m8n8.x4.shared.b16 {%0,%1,%2,%3}, [%4];"
                 : "=r"(r[0]), "=r"(r[1]), "=r"(r[2]), "=r"(r[3]) : "r"(addr));
}
__device__ __forceinline__ void mma16816(float c[4], const uint32_t a[4],
                                         uint32_t b0, uint32_t b1) {
    asm volatile("mma.sync.aligned.m16n8k16.row.col.f32.f16.f16.f32 "
                 "{%0,%1,%2,%3}, {%4,%5,%6,%7}, {%8,%9}, {%0,%1,%2,%3};"
                 : "+f"(c[0]), "+f"(c[1]), "+f"(c[2]), "+f"(c[3])
                 : "r"(a[0]), "r"(a[1]), "r"(a[2]), "r"(a[3]), "r"(b0), "r"(b1));
}
__device__ __forceinline__ float fast_tanh(float x) {
    float e = __expf(2.0f * x);
    return 1.0f - __fdividef(2.0f, e + 1.0f);
}
__device__ __forceinline__ float gelu_tanh(float v) {
    float u = 0.7978845608028654f * (v + 0.044715f * v * v * v);
    return 0.5f * v * (1.0f + fast_tanh(u));
}

// ---------------- staging (cp.async, 512 threads) ----------------
__device__ __forceinline__ void stageX(uint32_t dst, const __half* src, int tid) {
    const char* s = (const char*)src;   // src pitch = DMODEL*2
    #pragma unroll
    for (int i = 0; i < 8; ++i) {
        int idx = i * NTHR + tid, r = idx >> 5, c = idx & 31;   // 128 rows x 32
        cp16(dst + r * PX + c * 16, s + (size_t)r * (DMODEL * 2) + c * 16);
    }
}
__device__ __forceinline__ void stage64(uint32_t dst, const __half* src, int tid) {
    const char* s = (const char*)src;   // src pitch = DD*2 = 512
    #pragma unroll
    for (int i = 0; i < 4; ++i) {
        int idx = i * NTHR + tid, r = idx >> 5, c = idx & 31;   // 64 rows x 32
        cp16(dst + r * PX + c * 16, s + (size_t)r * 512 + c * 16);
    }
}
__device__ __forceinline__ void stage128(uint32_t dst, const __half* src, int tid) {
    const char* s = (const char*)src;   // src pitch = HH*2 = 2048
    #pragma unroll
    for (int i = 0; i < 2; ++i) {
        int idx = i * NTHR + tid, r = idx >> 3, c = idx & 7;    // 128 rows x 8
        cp16(dst + r * PW2 + c * 16, s + (size_t)r * 2048 + c * 16);
    }
}
__device__ __forceinline__ void stage_w2(uint32_t sb, int j, int s, bool isKan,
                                         int e, int m, int tid) {
    int half = s & 1;
    size_t off;
    const __half *sh, *sl;
    if (isKan) {
        off = ((size_t)(e * 3 + (s >> 1)) * DD + half * 128) * HH + j * 64;
        sh = g_w2kh + off; sl = g_w2kl + off;
    } else {
        off = ((size_t)m * DD + half * 128) * HH + j * 64;
        sh = g_w2mh + off; sl = g_w2ml + off;
    }
    uint32_t d = sb + SM_W2H + half * 18432;
    stage128(d, sh, tid);
    stage128(d + DW2L, sl, tid);
}

// ---------------- prologue kernels ----------------
__global__ void c0_kernel(const float* __restrict__ kpw, const float* __restrict__ kb) {
    int e = blockIdx.x, o = threadIdx.x;
    const float* w0 = kpw + (size_t)e * 4 * HH * DD;
    float s = kb[e * DD + o];
    for (int h = 0; h < HH; ++h) s += w0[(size_t)h * DD + o];
    g_c0[e * DD + o] = s;
}
__global__ void xhalf(const float* __restrict__ x) {
    size_t i = ((size_t)blockIdx.x * 256 + threadIdx.x) * 4;
    float4 v = *(const float4*)(x + i);
    *(__half2*)(g_x + i)     = __floats2half2_rn(v.x, v.y);
    *(__half2*)(g_x + i + 2) = __floats2half2_rn(v.z, v.w);
}
__device__ __forceinline__ void tsplit_body(const float* src, __half* dh,
                                            __half* dl, int K, int N) {
    __shared__ float ts[32][33];
    int k0 = blockIdx.x * 32, n0 = blockIdx.y * 32;
    int tx = threadIdx.x, ty = threadIdx.y;
    #pragma unroll
    for (int i = 0; i < 4; ++i)
        ts[ty + 8 * i][tx] = src[(size_t)(k0 + ty + 8 * i) * N + n0 + tx];
    __syncthreads();
    #pragma unroll
    for (int i = 0; i < 4; ++i) {
        int n = n0 + ty + 8 * i, k = k0 + tx;
        float v = ts[tx][ty + 8 * i] * WSC;
        __half h = __float2half(v);
        dh[(size_t)n * K + k] = h;
        dl[(size_t)n * K + k] = __float2half(v - __half2float(h));
    }
}
__global__ void tsplit_w1(const float* __restrict__ klw, const float* __restrict__ mw1) {
    int e = blockIdx.z;
    const float* src = (e < NKAN) ? klw + (size_t)e * DD * HH
                                  : mw1 + (size_t)(e - NKAN) * DD * HH;
    tsplit_body(src, g_w1h + (size_t)e * HH * DD, g_w1l + (size_t)e * HH * DD, DD, HH);
}
__global__ void tsplit_w2m(const float* __restrict__ mw2) {
    int z = blockIdx.z;
    tsplit_body(mw2 + (size_t)z * HH * DD,
                g_w2mh + (size_t)z * DD * HH, g_w2ml + (size_t)z * DD * HH, HH, DD);
}
__global__ void tsplit_w2k(const float* __restrict__ kpw) {
    int z = blockIdx.z, e = z / 3, p = z % 3 + 1;
    tsplit_body(kpw + (size_t)(e * 4 + p) * HH * DD,
                g_w2kh + (size_t)z * DD * HH, g_w2kl + (size_t)z * DD * HH, HH, DD);
}

// ---------------- main fused kernel: 128-token tile, 16 warps ----------------
__global__ void __launch_bounds__(NTHR, 1)
ffn_mma(const float* __restrict__ mlp_b1, const float* __restrict__ mlp_b2,
        float* __restrict__ out) {
    extern __shared__ __align__(16) char smc[];
    const uint32_t sb = smem_u32(smc);
    const int tid = threadIdx.x, wid = tid >> 5, lane = tid & 31;
    const int e = blockIdx.y, tile = blockIdx.x, t0 = tile * MT;
    const bool isKan = (e < NKAN);
    const int m = e - NKAN;
    const int npoly = isKan ? 3 : 1;
    const int ns = 2 * npoly;
    const int wm = wid & 3, wn = wid >> 2;   // 4 x 4 warp grid

    {
        stageX(sb + SM_X, g_x + (size_t)t0 * DMODEL + e * DD, tid);
        CP_COMMIT();
        size_t w1off = (size_t)e * HH * DD;
        stage64(sb + SM_W1H, g_w1h + w1off, tid);
        stage64(sb + SM_W1L, g_w1l + w1off, tid);
        CP_COMMIT();
        stage_w2(sb, 0, 0, isKan, e, m, tid); CP_COMMIT();
        stage_w2(sb, 0, 1, isKan, e, m, tid); CP_COMMIT();
    }

    float acc[2][2][4][4];
    #pragma unroll
    for (int a = 0; a < 2; ++a)
        #pragma unroll
        for (int b = 0; b < 2; ++b)
            #pragma unroll
            for (int c = 0; c < 4; ++c)
                #pragma unroll
                for (int d = 0; d < 4; ++d) acc[a][b][c][d] = 0.f;

    const int lr = (lane & 7) + 8 * ((lane >> 3) & 1);
    const int lk = (lane >> 4) * 16;
    const uint32_t aX  = sb + SM_X   + (32 * wm + lr) * PX  + lk;
    const uint32_t aW1 = sb + SM_W1H + (16 * wn + lr) * PX  + lk;
    const uint32_t aA  = sb + SM_A   + (32 * wm + lr) * PW2 + lk;
    const uint32_t aW2 = sb + SM_W2H + (32 * wn + lr) * PW2 + lk;

    for (int j = 0; j < 16; ++j) {
        if (isKan && j) { CP_WAIT(6); } else { CP_WAIT(2); }
        __syncthreads();

        // ---- GEMM1: A(fp16)[128x256] x (W1h + W1l)[256x64], warp tile 32x16 ----
        float c1[2][2][4];
        #pragma unroll
        for (int a = 0; a < 2; ++a)
            #pragma unroll
            for (int b = 0; b < 2; ++b)
                #pragma unroll
                for (int c = 0; c < 4; ++c) c1[a][b][c] = 0.f;

        #pragma unroll
        for (int kk = 0; kk < 16; ++kk) {
            uint32_t fa[8], fb[8];
            ldsm4(aX + kk * 32, fa);
            ldsm4(aX + 16 * PX + kk * 32, fa + 4);
            ldsm4(aW1 + kk * 32, fb);
            ldsm4(aW1 + DW1L + kk * 32, fb + 4);
            mma16816(c1[0][0], fa + 0, fb[0], fb[2]);
            mma16816(c1[0][1], fa + 0, fb[1], fb[3]);
            mma16816(c1[1][0], fa + 4, fb[0], fb[2]);
            mma16816(c1[1][1], fa + 4, fb[1], fb[3]);
            mma16816(c1[0][0], fa + 0, fb[4], fb[6]);
            mma16816(c1[0][1], fa + 0, fb[5], fb[7]);
            mma16816(c1[1][0], fa + 4, fb[4], fb[6]);
            mma16816(c1[1][1], fa + 4, fb[5], fb[7]);
        }
        __syncthreads();
        if (j < 15) {
            size_t w1off = ((size_t)e * HH + (j + 1) * 64) * DD;
            stage64(sb + SM_W1H, g_w1h + w1off, tid);
            stage64(sb + SM_W1L, g_w1l + w1off, tid);
            CP_COMMIT();
        }

        // ---- activation base values, in place (undo x64 weight scale) ----
        if (isKan) {
            #pragma unroll
            for (int a = 0; a < 2; ++a)
                #pragma unroll
                for (int b = 0; b < 2; ++b)
                    #pragma unroll
                    for (int c = 0; c < 4; ++c)
                        c1[a][b][c] = fast_tanh(c1[a][b][c] * WSCI);
        } else {
            #pragma unroll
            for (int nt = 0; nt < 2; ++nt) {
                int col = j * 64 + 16 * wn + 8 * nt + 2 * (lane & 3);
                float2 bv = *(const float2*)(mlp_b1 + (size_t)m * HH + col);
                #pragma unroll
                for (int a = 0; a < 2; ++a) {
                    c1[a][nt][0] = gelu_tanh(c1[a][nt][0] * WSCI + bv.x);
                    c1[a][nt][1] = gelu_tanh(c1[a][nt][1] * WSCI + bv.y);
                    c1[a][nt][2] = gelu_tanh(c1[a][nt][2] * WSCI + bv.x);
                    c1[a][nt][3] = gelu_tanh(c1[a][nt][3] * WSCI + bv.y);
                }
            }
        }

        for (int p = 1; p <= npoly; ++p) {
            #pragma unroll
            for (int a = 0; a < 2; ++a)
                #pragma unroll
                for (int nt = 0; nt < 2; ++nt) {
                    float v[4];
                    #pragma unroll
                    for (int c = 0; c < 4; ++c) {
                        float t = c1[a][nt][c];
                        v[c] = (p == 1) ? t
                             : (p == 2) ? fmaf(2.f * t, t, -1.f)
                                        : t * fmaf(4.f * t, t, -3.f);
                    }
                    int rowb = 32 * wm + 16 * a + (lane >> 2);
                    int colb = (16 * wn + 8 * nt + 2 * (lane & 3)) * 2;
                    *(__half2*)(smc + SM_A + rowb * PW2 + colb) = __floats2half2_rn(v[0], v[1]);
                    *(__half2*)(smc + SM_A + (rowb + 8) * PW2 + colb) = __floats2half2_rn(v[2], v[3]);
                }

            #pragma unroll
            for (int sub = 0; sub < 2; ++sub) {
                int s = (p - 1) * 2 + sub;
                if (s < 2) { CP_WAIT(2); } else { CP_WAIT(1); }
                __syncthreads();
                const uint32_t w2b = aW2 + sub * 18432;
                #pragma unroll
                for (int kk = 0; kk < 4; ++kk) {
                    uint32_t Fa[8], Fb[16];
                    ldsm4(aA + kk * 32, Fa);
                    ldsm4(aA + 16 * PW2 + kk * 32, Fa + 4);
                    ldsm4(w2b + kk * 32, Fb);
                    ldsm4(w2b + 16 * PW2 + kk * 32, Fb + 4);
                    ldsm4(w2b + DW2L + kk * 32, Fb + 8);
                    ldsm4(w2b + DW2L + 16 * PW2 + kk * 32, Fb + 12);
                    // hi term: 8-tile round robin
                    #pragma unroll
                    for (int a = 0; a < 2; ++a)
                        #pragma unroll
                        for (int nt = 0; nt < 4; ++nt)
                            mma16816(acc[sub][a][nt], Fa + a * 4,
                                     Fb[4 * (nt >> 1) + (nt & 1)],
                                     Fb[4 * (nt >> 1) + (nt & 1) + 2]);
                    // lo term
                    #pragma unroll
                    for (int a = 0; a < 2; ++a)
                        #pragma unroll
                        for (int nt = 0; nt < 4; ++nt)
                            mma16816(acc[sub][a][nt], Fa + a * 4,
                                     Fb[8 + 4 * (nt >> 1) + (nt & 1)],
                                     Fb[8 + 4 * (nt >> 1) + (nt & 1) + 2]);
                }
                __syncthreads();
                int ss = s + 2;
                if (ss < ns) { stage_w2(sb, j, ss, isKan, e, m, tid); CP_COMMIT(); }
                else if (j < 15) { stage_w2(sb, j + 1, ss - ns, isKan, e, m, tid); CP_COMMIT(); }
            }
        }
    }

    // ---- epilogue: out = acc/64 + bias ----
    const float* bp = isKan ? (g_c0 + e * DD) : (mlp_b2 + (size_t)m * DD);
    #pragma unroll
    for (int sub = 0; sub < 2; ++sub)
        #pragma unroll
        for (int a = 0; a < 2; ++a)
            #pragma unroll
            for (int nt = 0; nt < 4; ++nt) {
                int row = t0 + 32 * wm + 16 * a + (lane >> 2);
                int col = sub * 128 + 32 * wn + 8 * nt + 2 * (lane & 3);
                float2 v0, v1;
                v0.x = acc[sub][a][nt][0] * WSCI + bp[col];
                v0.y = acc[sub][a][nt][1] * WSCI + bp[col + 1];
                v1.x = acc[sub][a][nt][2] * WSCI + bp[col];
                v1.y = acc[sub][a][nt][3] * WSCI + bp[col + 1];
                *(float2*)(out + (size_t)row * DMODEL + e * DD + col) = v0;
                *(float2*)(out + (size_t)(row + 8) * DMODEL + e * DD + col) = v1;
            }
}

extern "C" void kernel_launch(void* const* d_in, const int* in_sizes, int n_in,
                              void* d_out, int out_size) {
    const float* x   = (const float*)d_in[0];
    const float* klw = (const float*)d_in[1];
    const float* kpw = (const float*)d_in[2];
    const float* kb  = (const float*)d_in[3];
    const float* w1  = (const float*)d_in[4];
    const float* b1  = (const float*)d_in[5];
    const float* w2  = (const float*)d_in[6];
    const float* b2  = (const float*)d_in[7];
    float* out = (float*)d_out;

    cudaFuncSetAttribute(ffn_mma, cudaFuncAttributeMaxDynamicSharedMemorySize, SM_TOTAL);

    c0_kernel<<<NKAN, DD>>>(kpw, kb);
    xhalf<<<TOK * DMODEL / 1024, 256>>>(x);
    tsplit_w1<<<dim3(DD / 32, HH / 32, EEXP), dim3(32, 8)>>>(klw, w1);
    tsplit_w2m<<<dim3(HH / 32, DD / 32, 6), dim3(32, 8)>>>(w2);
    tsplit_w2k<<<dim3(HH / 32, DD / 32, 6), dim3(32, 8)>>>(kpw);
    ffn_mma<<<dim3(TOK / MT, EEXP), NTHR, SM_TOTAL>>>(b1, b2, out);
}

// round 8
// speedup vs baseline: 4.6895x; 1.3221x over previous
#include <cuda_runtime.h>
#include <cuda_fp16.h>
#include <math.h>
#include <stdint.h>

#define TOK    16384
#define DMODEL 2048
#define EEXP   8
#define NKAN   2
#define DD     256
#define HH     1024
#define MT     128
#define NTHR   512
#define WSC    64.0f
#define WSCI   (1.0f / 64.0f)

// ---------------- global scratch (fp16; weights pre-scaled x64) ----------------
__device__ __align__(16) __half g_x[(size_t)TOK * DMODEL];
__device__ __align__(16) __half g_w1h[(size_t)EEXP * HH * DD];   // [e][h][d]
__device__ __align__(16) __half g_w1l[(size_t)EEXP * HH * DD];
__device__ __align__(16) __half g_w2mh[(size_t)6 * DD * HH];     // [m][o][h]  (hi only used)
__device__ __align__(16) __half g_w2kh[(size_t)6 * DD * HH];     // [e*3+p-1][o][h]
__device__ float g_c0[NKAN * DD];

// ---------------- smem layout (bytes) ----------------
#define PX     528
#define PW2    144
#define SM_X   0                      // 128 x 528 = 67584
#define SM_W1H 67584                  // 64 x 528 = 33792
#define SM_W1L 101376
#define SM_W2H 135168                 // 2 halves x 128 x 144 = 36864
#define SM_A   172032                 // 128 x 144 = 18432
#define SM_TOTAL 190464
#define DW1L  33792

// ---------------- PTX helpers ----------------
__device__ __forceinline__ uint32_t smem_u32(const void* p) {
    uint32_t a;
    asm("{ .reg .u64 t; cvta.to.shared.u64 t, %1; cvt.u32.u64 %0, t; }" : "=r"(a) : "l"(p));
    return a;
}
__device__ __forceinline__ void cp16(uint32_t d, const void* s) {
    asm volatile("cp.async.cg.shared.global [%0], [%1], 16;" :: "r"(d), "l"(s));
}
#define CP_COMMIT() asm volatile("cp.async.commit_group;" ::: "memory")
#define CP_WAIT(N)  asm volatile("cp.async.wait_group %0;" :: "n"(N) : "memory")

__device__ __forceinline__ void ldsm4(uint32_t addr, uint32_t* r) {
    asm volatile("ldmatrix.sync.aligned.m8n8.x4.shared.b16 {%0,%1,%2,%3}, [%4];"
                 : "=r"(r[0]), "=r"(r[1]), "=r"(r[2]), "=r"(r[3]) : "r"(addr));
}
__device__ __forceinline__ void mma16816(float c[4], const uint32_t a[4],
                                         uint32_t b0, uint32_t b1) {
    asm volatile("mma.sync.aligned.m16n8k16.row.col.f32.f16.f16.f32 "
                 "{%0,%1,%2,%3}, {%4,%5,%6,%7}, {%8,%9}, {%0,%1,%2,%3};"
                 : "+f"(c[0]), "+f"(c[1]), "+f"(c[2]), "+f"(c[3])
                 : "r"(a[0]), "r"(a[1]), "r"(a[2]), "r"(a[3]), "r"(b0), "r"(b1));
}
__device__ __forceinline__ float fast_tanh(float x) {
    float e = __expf(2.0f * x);
    return 1.0f - __fdividef(2.0f, e + 1.0f);
}
__device__ __forceinline__ float gelu_tanh(float v) {
    float u = 0.7978845608028654f * (v + 0.044715f * v * v * v);
    return 0.5f * v * (1.0f + fast_tanh(u));
}

// ---------------- staging (cp.async, 512 threads) ----------------
__device__ __forceinline__ void stageX(uint32_t dst, const __half* src, int tid) {
    const char* s = (const char*)src;
    #pragma unroll
    for (int i = 0; i < 8; ++i) {
        int idx = i * NTHR + tid, r = idx >> 5, c = idx & 31;   // 128 rows x 32
        cp16(dst + r * PX + c * 16, s + (size_t)r * (DMODEL * 2) + c * 16);
    }
}
__device__ __forceinline__ void stage64(uint32_t dst, const __half* src, int tid) {
    const char* s = (const char*)src;   // pitch 512 B
    #pragma unroll
    for (int i = 0; i < 4; ++i) {
        int idx = i * NTHR + tid, r = idx >> 5, c = idx & 31;   // 64 rows x 32
        cp16(dst + r * PX + c * 16, s + (size_t)r * 512 + c * 16);
    }
}
__device__ __forceinline__ void stage128(uint32_t dst, const __half* src, int tid) {
    const char* s = (const char*)src;   // pitch 2048 B
    #pragma unroll
    for (int i = 0; i < 2; ++i) {
        int idx = i * NTHR + tid, r = idx >> 3, c = idx & 7;    // 128 rows x 8
        cp16(dst + r * PW2 + c * 16, s + (size_t)r * 2048 + c * 16);
    }
}
__device__ __forceinline__ void stage_w2(uint32_t sb, int j, int s, bool isKan,
                                         int e, int m, int tid) {
    int half = s & 1;
    const __half* sh;
    if (isKan)
        sh = g_w2kh + ((size_t)(e * 3 + (s >> 1)) * DD + half * 128) * HH + j * 64;
    else
        sh = g_w2mh + ((size_t)m * DD + half * 128) * HH + j * 64;
    stage128(sb + SM_W2H + half * 18432, sh, tid);
}

// ---------------- prologue kernels ----------------
__global__ void c0_kernel(const float* __restrict__ kpw, const float* __restrict__ kb) {
    int e = blockIdx.x, o = threadIdx.x;
    const float* w0 = kpw + (size_t)e * 4 * HH * DD;
    float s = kb[e * DD + o];
    for (int h = 0; h < HH; ++h) s += w0[(size_t)h * DD + o];
    g_c0[e * DD + o] = s;
}
__global__ void xhalf(const float* __restrict__ x) {
    size_t i = ((size_t)blockIdx.x * 256 + threadIdx.x) * 4;
    float4 v = *(const float4*)(x + i);
    *(__half2*)(g_x + i)     = __floats2half2_rn(v.x, v.y);
    *(__half2*)(g_x + i + 2) = __floats2half2_rn(v.z, v.w);
}
// transpose+split (scaled by WSC): hi+lo
__device__ __forceinline__ void tsplit_body(const float* src, __half* dh,
                                            __half* dl, int K, int N) {
    __shared__ float ts[32][33];
    int k0 = blockIdx.x * 32, n0 = blockIdx.y * 32;
    int tx = threadIdx.x, ty = threadIdx.y;
    #pragma unroll
    for (int i = 0; i < 4; ++i)
        ts[ty + 8 * i][tx] = src[(size_t)(k0 + ty + 8 * i) * N + n0 + tx];
    __syncthreads();
    #pragma unroll
    for (int i = 0; i < 4; ++i) {
        int n = n0 + ty + 8 * i, k = k0 + tx;
        float v = ts[tx][ty + 8 * i] * WSC;
        __half h = __float2half(v);
        dh[(size_t)n * K + k] = h;
        if (dl) dl[(size_t)n * K + k] = __float2half(v - __half2float(h));
    }
}
__global__ void tsplit_w1(const float* __restrict__ klw, const float* __restrict__ mw1) {
    int e = blockIdx.z;
    const float* src = (e < NKAN) ? klw + (size_t)e * DD * HH
                                  : mw1 + (size_t)(e - NKAN) * DD * HH;
    tsplit_body(src, g_w1h + (size_t)e * HH * DD, g_w1l + (size_t)e * HH * DD, DD, HH);
}
__global__ void tsplit_w2m(const float* __restrict__ mw2) {
    int z = blockIdx.z;
    tsplit_body(mw2 + (size_t)z * HH * DD, g_w2mh + (size_t)z * DD * HH, nullptr, HH, DD);
}
__global__ void tsplit_w2k(const float* __restrict__ kpw) {
    int z = blockIdx.z, e = z / 3, p = z % 3 + 1;
    tsplit_body(kpw + (size_t)(e * 4 + p) * HH * DD,
                g_w2kh + (size_t)z * DD * HH, nullptr, HH, DD);
}

// ---------------- main fused kernel: 128-token tile, 16 warps ----------------
__global__ void __launch_bounds__(NTHR, 1)
ffn_mma(const float* __restrict__ mlp_b1, const float* __restrict__ mlp_b2,
        float* __restrict__ out) {
    extern __shared__ __align__(16) char smc[];
    const uint32_t sb = smem_u32(smc);
    const int tid = threadIdx.x, wid = tid >> 5, lane = tid & 31;
    const int e = blockIdx.y, tile = blockIdx.x, t0 = tile * MT;
    const bool isKan = (e < NKAN);
    const int m = e - NKAN;
    const int npoly = isKan ? 3 : 1;
    const int ns = 2 * npoly;
    const int wm = wid & 3, wn = wid >> 2;   // 4 x 4 warp grid

    {
        stageX(sb + SM_X, g_x + (size_t)t0 * DMODEL + e * DD, tid);
        CP_COMMIT();
        size_t w1off = (size_t)e * HH * DD;
        stage64(sb + SM_W1H, g_w1h + w1off, tid);
        stage64(sb + SM_W1L, g_w1l + w1off, tid);
        CP_COMMIT();
        stage_w2(sb, 0, 0, isKan, e, m, tid); CP_COMMIT();
        stage_w2(sb, 0, 1, isKan, e, m, tid); CP_COMMIT();
    }

    float acc[2][2][4][4];
    #pragma unroll
    for (int a = 0; a < 2; ++a)
        #pragma unroll
        for (int b = 0; b < 2; ++b)
            #pragma unroll
            for (int c = 0; c < 4; ++c)
                #pragma unroll
                for (int d = 0; d < 4; ++d) acc[a][b][c][d] = 0.f;

    const int lr = (lane & 7) + 8 * ((lane >> 3) & 1);
    const int lk = (lane >> 4) * 16;
    const uint32_t aX  = sb + SM_X   + (32 * wm + lr) * PX  + lk;
    const uint32_t aW1 = sb + SM_W1H + (16 * wn + lr) * PX  + lk;
    const uint32_t aA  = sb + SM_A   + (32 * wm + lr) * PW2 + lk;
    const uint32_t aW2 = sb + SM_W2H + (32 * wn + lr) * PW2 + lk;

    for (int j = 0; j < 16; ++j) {
        if (isKan && j) { CP_WAIT(6); } else { CP_WAIT(2); }
        __syncthreads();

        // ---- GEMM1: A(fp16)[128x256] x (W1h + W1l)[256x64], warp tile 32x16 ----
        float c1[2][2][4];
        #pragma unroll
        for (int a = 0; a < 2; ++a)
            #pragma unroll
            for (int b = 0; b < 2; ++b)
                #pragma unroll
                for (int c = 0; c < 4; ++c) c1[a][b][c] = 0.f;

        #pragma unroll
        for (int kk = 0; kk < 16; ++kk) {
            uint32_t fa[8], fb[8];
            ldsm4(aX + kk * 32, fa);
            ldsm4(aX + 16 * PX + kk * 32, fa + 4);
            ldsm4(aW1 + kk * 32, fb);
            ldsm4(aW1 + DW1L + kk * 32, fb + 4);
            mma16816(c1[0][0], fa + 0, fb[0], fb[2]);
            mma16816(c1[0][1], fa + 0, fb[1], fb[3]);
            mma16816(c1[1][0], fa + 4, fb[0], fb[2]);
            mma16816(c1[1][1], fa + 4, fb[1], fb[3]);
            mma16816(c1[0][0], fa + 0, fb[4], fb[6]);
            mma16816(c1[0][1], fa + 0, fb[5], fb[7]);
            mma16816(c1[1][0], fa + 4, fb[4], fb[6]);
            mma16816(c1[1][1], fa + 4, fb[5], fb[7]);
        }
        __syncthreads();
        if (j < 15) {
            size_t w1off = ((size_t)e * HH + (j + 1) * 64) * DD;
            stage64(sb + SM_W1H, g_w1h + w1off, tid);
            stage64(sb + SM_W1L, g_w1l + w1off, tid);
            CP_COMMIT();
        }

        // ---- activation, in place (undo x64 weight scale) ----
        if (isKan) {
            #pragma unroll
            for (int a = 0; a < 2; ++a)
                #pragma unroll
                for (int b = 0; b < 2; ++b)
                    #pragma unroll
                    for (int c = 0; c < 4; ++c)
                        c1[a][b][c] = fast_tanh(c1[a][b][c] * WSCI);
        } else {
            #pragma unroll
            for (int nt = 0; nt < 2; ++nt) {
                int col = j * 64 + 16 * wn + 8 * nt + 2 * (lane & 3);
                float2 bv = *(const float2*)(mlp_b1 + (size_t)m * HH + col);
                #pragma unroll
                for (int a = 0; a < 2; ++a) {
                    c1[a][nt][0] = gelu_tanh(c1[a][nt][0] * WSCI + bv.x);
                    c1[a][nt][1] = gelu_tanh(c1[a][nt][1] * WSCI + bv.y);
                    c1[a][nt][2] = gelu_tanh(c1[a][nt][2] * WSCI + bv.x);
                    c1[a][nt][3] = gelu_tanh(c1[a][nt][3] * WSCI + bv.y);
                }
            }
        }

        for (int p = 1; p <= npoly; ++p) {
            #pragma unroll
            for (int a = 0; a < 2; ++a)
                #pragma unroll
                for (int nt = 0; nt < 2; ++nt) {
                    float v[4];
                    #pragma unroll
                    for (int c = 0; c < 4; ++c) {
                        float t = c1[a][nt][c];
                        v[c] = (p == 1) ? t
                             : (p == 2) ? fmaf(2.f * t, t, -1.f)
                                        : t * fmaf(4.f * t, t, -3.f);
                    }
                    int rowb = 32 * wm + 16 * a + (lane >> 2);
                    int colb = (16 * wn + 8 * nt + 2 * (lane & 3)) * 2;
                    *(__half2*)(smc + SM_A + rowb * PW2 + colb) = __floats2half2_rn(v[0], v[1]);
                    *(__half2*)(smc + SM_A + (rowb + 8) * PW2 + colb) = __floats2half2_rn(v[2], v[3]);
                }

            #pragma unroll
            for (int sub = 0; sub < 2; ++sub) {
                int s = (p - 1) * 2 + sub;
                if (s < 2) { CP_WAIT(2); } else { CP_WAIT(1); }
                __syncthreads();
                const uint32_t w2b = aW2 + sub * 18432;
                #pragma unroll
                for (int kk = 0; kk < 4; ++kk) {
                    uint32_t Fa[8], Fb[8];
                    ldsm4(aA + kk * 32, Fa);
                    ldsm4(aA + 16 * PW2 + kk * 32, Fa + 4);
                    ldsm4(w2b + kk * 32, Fb);
                    ldsm4(w2b + 16 * PW2 + kk * 32, Fb + 4);
                    #pragma unroll
                    for (int a = 0; a < 2; ++a)
                        #pragma unroll
                        for (int nt = 0; nt < 4; ++nt)
                            mma16816(acc[sub][a][nt], Fa + a * 4,
                                     Fb[4 * (nt >> 1) + (nt & 1)],
                                     Fb[4 * (nt >> 1) + (nt & 1) + 2]);
                }
                __syncthreads();
                int ss = s + 2;
                if (ss < ns) { stage_w2(sb, j, ss, isKan, e, m, tid); CP_COMMIT(); }
                else if (j < 15) { stage_w2(sb, j + 1, ss - ns, isKan, e, m, tid); CP_COMMIT(); }
            }
        }
    }

    // ---- epilogue: out = acc/64 + bias ----
    const float* bp = isKan ? (g_c0 + e * DD) : (mlp_b2 + (size_t)m * DD);
    #pragma unroll
    for (int sub = 0; sub < 2; ++sub)
        #pragma unroll
        for (int a = 0; a < 2; ++a)
            #pragma unroll
            for (int nt = 0; nt < 4; ++nt) {
                int row = t0 + 32 * wm + 16 * a + (lane >> 2);
                int col = sub * 128 + 32 * wn + 8 * nt + 2 * (lane & 3);
                float2 v0, v1;
                v0.x = acc[sub][a][nt][0] * WSCI + bp[col];
                v0.y = acc[sub][a][nt][1] * WSCI + bp[col + 1];
                v1.x = acc[sub][a][nt][2] * WSCI + bp[col];
                v1.y = acc[sub][a][nt][3] * WSCI + bp[col + 1];
                *(float2*)(out + (size_t)row * DMODEL + e * DD + col) = v0;
                *(float2*)(out + (size_t)(row + 8) * DMODEL + e * DD + col) = v1;
            }
}

extern "C" void kernel_launch(void* const* d_in, const int* in_sizes, int n_in,
                              void* d_out, int out_size) {
    const float* x   = (const float*)d_in[0];
    const float* klw = (const float*)d_in[1];
    const float* kpw = (const float*)d_in[2];
    const float* kb  = (const float*)d_in[3];
    const float* w1  = (const float*)d_in[4];
    const float* b1  = (const float*)d_in[5];
    const float* w2  = (const float*)d_in[6];
    const float* b2  = (const float*)d_in[7];
    float* out = (float*)d_out;

    cudaFuncSetAttribute(ffn_mma, cudaFuncAttributeMaxDynamicSharedMemorySize, SM_TOTAL);

    c0_kernel<<<NKAN, DD>>>(kpw, kb);
    xhalf<<<TOK * DMODEL / 1024, 256>>>(x);
    tsplit_w1<<<dim3(DD / 32, HH / 32, EEXP), dim3(32, 8)>>>(klw, w1);
    tsplit_w2m<<<dim3(HH / 32, DD / 32, 6), dim3(32, 8)>>>(w2);
    tsplit_w2k<<<dim3(HH / 32, DD / 32, 6), dim3(32, 8)>>>(kpw);
    ffn_mma<<<dim3(TOK / MT, EEXP), NTHR, SM_TOTAL>>>(b1, b2, out);
}

// round 9
// speedup vs baseline: 5.6678x; 1.2086x over previous
#include <cuda_runtime.h>
#include <cuda_fp16.h>
#include <math.h>
#include <stdint.h>

#define TOK    16384
#define DMODEL 2048
#define EEXP   8
#define NKAN   2
#define DD     256
#define HH     1024
#define MT     128
#define NTHR   512
#define WSC    64.0f
#define WSCI   (1.0f / 64.0f)

// ---------------- global scratch (fp16; weights pre-scaled x64) ----------------
__device__ __align__(16) __half g_x[(size_t)TOK * DMODEL];
__device__ __align__(16) __half g_w1h[(size_t)EEXP * HH * DD];   // [e][h][d]
__device__ __align__(16) __half g_w2mh[(size_t)6 * DD * HH];     // [m][o][h]
__device__ __align__(16) __half g_w2kh[(size_t)6 * DD * HH];     // [e*3+p-1][o][h]
__device__ float g_c0[NKAN * DD];

// ---------------- smem layout (bytes) ----------------
#define PX     528
#define PW2    144
#define SM_X   0                      // 128 x 528 = 67584
#define SM_W1H 67584                  // 64 x 528 = 33792
#define SM_W2H 101376                 // 2 halves x 128 x 144 = 36864
#define SM_A   138240                 // 128 x 144 = 18432
#define SM_TOTAL 156672

// ---------------- PTX helpers ----------------
__device__ __forceinline__ uint32_t smem_u32(const void* p) {
    uint32_t a;
    asm("{ .reg .u64 t; cvta.to.shared.u64 t, %1; cvt.u32.u64 %0, t; }" : "=r"(a) : "l"(p));
    return a;
}
__device__ __forceinline__ void cp16(uint32_t d, const void* s) {
    asm volatile("cp.async.cg.shared.global [%0], [%1], 16;" :: "r"(d), "l"(s));
}
#define CP_COMMIT() asm volatile("cp.async.commit_group;" ::: "memory")
#define CP_WAIT(N)  asm volatile("cp.async.wait_group %0;" :: "n"(N) : "memory")

__device__ __forceinline__ void ldsm4(uint32_t addr, uint32_t* r) {
    asm volatile("ldmatrix.sync.aligned.m8n8.x4.shared.b16 {%0,%1,%2,%3}, [%4];"
                 : "=r"(r[0]), "=r"(r[1]), "=r"(r[2]), "=r"(r[3]) : "r"(addr));
}
__device__ __forceinline__ void mma16816(float c[4], const uint32_t a[4],
                                         uint32_t b0, uint32_t b1) {
    asm volatile("mma.sync.aligned.m16n8k16.row.col.f32.f16.f16.f32 "
                 "{%0,%1,%2,%3}, {%4,%5,%6,%7}, {%8,%9}, {%0,%1,%2,%3};"
                 : "+f"(c[0]), "+f"(c[1]), "+f"(c[2]), "+f"(c[3])
                 : "r"(a[0]), "r"(a[1]), "r"(a[2]), "r"(a[3]), "r"(b0), "r"(b1));
}
__device__ __forceinline__ float fast_tanh(float x) {
    float e = __expf(2.0f * x);
    return 1.0f - __fdividef(2.0f, e + 1.0f);
}
__device__ __forceinline__ float gelu_tanh(float v) {
    float u = 0.7978845608028654f * (v + 0.044715f * v * v * v);
    return 0.5f * v * (1.0f + fast_tanh(u));
}

// ---------------- staging (cp.async, 512 threads) ----------------
__device__ __forceinline__ void stageX(uint32_t dst, const __half* src, int tid) {
    const char* s = (const char*)src;
    #pragma unroll
    for (int i = 0; i < 8; ++i) {
        int idx = i * NTHR + tid, r = idx >> 5, c = idx & 31;   // 128 rows x 32
        cp16(dst + r * PX + c * 16, s + (size_t)r * (DMODEL * 2) + c * 16);
    }
}
__device__ __forceinline__ void stage64(uint32_t dst, const __half* src, int tid) {
    const char* s = (const char*)src;   // pitch 512 B
    #pragma unroll
    for (int i = 0; i < 4; ++i) {
        int idx = i * NTHR + tid, r = idx >> 5, c = idx & 31;   // 64 rows x 32
        cp16(dst + r * PX + c * 16, s + (size_t)r * 512 + c * 16);
    }
}
__device__ __forceinline__ void stage128(uint32_t dst, const __half* src, int tid) {
    const char* s = (const char*)src;   // pitch 2048 B
    #pragma unroll
    for (int i = 0; i < 2; ++i) {
        int idx = i * NTHR + tid, r = idx >> 3, c = idx & 7;    // 128 rows x 8
        cp16(dst + r * PW2 + c * 16, s + (size_t)r * 2048 + c * 16);
    }
}
__device__ __forceinline__ void stage_w2(uint32_t sb, int j, int s, bool isKan,
                                         int e, int m, int tid) {
    int half = s & 1;
    const __half* sh;
    if (isKan)
        sh = g_w2kh + ((size_t)(e * 3 + (s >> 1)) * DD + half * 128) * HH + j * 64;
    else
        sh = g_w2mh + ((size_t)m * DD + half * 128) * HH + j * 64;
    stage128(sb + SM_W2H + half * 18432, sh, tid);
}

// ---------------- prologue kernels ----------------
__global__ void c0_kernel(const float* __restrict__ kpw, const float* __restrict__ kb) {
    int e = blockIdx.x, o = threadIdx.x;
    const float* w0 = kpw + (size_t)e * 4 * HH * DD;
    float s = kb[e * DD + o];
    for (int h = 0; h < HH; ++h) s += w0[(size_t)h * DD + o];
    g_c0[e * DD + o] = s;
}
__global__ void xhalf(const float* __restrict__ x) {
    size_t i = ((size_t)blockIdx.x * 256 + threadIdx.x) * 4;
    float4 v = *(const float4*)(x + i);
    *(__half2*)(g_x + i)     = __floats2half2_rn(v.x, v.y);
    *(__half2*)(g_x + i + 2) = __floats2half2_rn(v.z, v.w);
}
// transpose (+WSC scale), hi only
__device__ __forceinline__ void tconv_body(const float* src, __half* dh, int K, int N) {
    __shared__ float ts[32][33];
    int k0 = blockIdx.x * 32, n0 = blockIdx.y * 32;
    int tx = threadIdx.x, ty = threadIdx.y;
    #pragma unroll
    for (int i = 0; i < 4; ++i)
        ts[ty + 8 * i][tx] = src[(size_t)(k0 + ty + 8 * i) * N + n0 + tx];
    __syncthreads();
    #pragma unroll
    for (int i = 0; i < 4; ++i) {
        int n = n0 + ty + 8 * i, k = k0 + tx;
        dh[(size_t)n * K + k] = __float2half(ts[tx][ty + 8 * i] * WSC);
    }
}
__global__ void tconv_w1(const float* __restrict__ klw, const float* __restrict__ mw1) {
    int e = blockIdx.z;
    const float* src = (e < NKAN) ? klw + (size_t)e * DD * HH
                                  : mw1 + (size_t)(e - NKAN) * DD * HH;
    tconv_body(src, g_w1h + (size_t)e * HH * DD, DD, HH);
}
__global__ void tconv_w2m(const float* __restrict__ mw2) {
    int z = blockIdx.z;
    tconv_body(mw2 + (size_t)z * HH * DD, g_w2mh + (size_t)z * DD * HH, HH, DD);
}
__global__ void tconv_w2k(const float* __restrict__ kpw) {
    int z = blockIdx.z, e = z / 3, p = z % 3 + 1;
    tconv_body(kpw + (size_t)(e * 4 + p) * HH * DD, g_w2kh + (size_t)z * DD * HH, HH, DD);
}

// ---------------- main fused kernel: 128-token tile, 16 warps ----------------
__global__ void __launch_bounds__(NTHR, 1)
ffn_mma(const float* __restrict__ mlp_b1, const float* __restrict__ mlp_b2,
        float* __restrict__ out) {
    extern __shared__ __align__(16) char smc[];
    const uint32_t sb = smem_u32(smc);
    const int tid = threadIdx.x, wid = tid >> 5, lane = tid & 31;
    const int e = blockIdx.y, tile = blockIdx.x, t0 = tile * MT;
    const bool isKan = (e < NKAN);
    const int m = e - NKAN;
    const int npoly = isKan ? 3 : 1;
    const int ns = 2 * npoly;
    const int wm = wid & 3, wn = wid >> 2;   // 4 x 4 warp grid

    {
        stageX(sb + SM_X, g_x + (size_t)t0 * DMODEL + e * DD, tid);
        CP_COMMIT();
        stage64(sb + SM_W1H, g_w1h + (size_t)e * HH * DD, tid);
        CP_COMMIT();
        stage_w2(sb, 0, 0, isKan, e, m, tid); CP_COMMIT();
        stage_w2(sb, 0, 1, isKan, e, m, tid); CP_COMMIT();
    }

    float acc[2][2][4][4];
    #pragma unroll
    for (int a = 0; a < 2; ++a)
        #pragma unroll
        for (int b = 0; b < 2; ++b)
            #pragma unroll
            for (int c = 0; c < 4; ++c)
                #pragma unroll
                for (int d = 0; d < 4; ++d) acc[a][b][c][d] = 0.f;

    const int lr = (lane & 7) + 8 * ((lane >> 3) & 1);
    const int lk = (lane >> 4) * 16;
    const uint32_t aX  = sb + SM_X   + (32 * wm + lr) * PX  + lk;
    const uint32_t aW1 = sb + SM_W1H + (16 * wn + lr) * PX  + lk;
    const uint32_t aA  = sb + SM_A   + (32 * wm + lr) * PW2 + lk;
    const uint32_t aW2 = sb + SM_W2H + (32 * wn + lr) * PW2 + lk;

    for (int j = 0; j < 16; ++j) {
        if (isKan && j) { CP_WAIT(6); } else { CP_WAIT(2); }
        __syncthreads();

        // ---- GEMM1: A(fp16)[128x256] x W1h[256x64], warp tile 32x16 ----
        float c1[2][2][4];
        #pragma unroll
        for (int a = 0; a < 2; ++a)
            #pragma unroll
            for (int b = 0; b < 2; ++b)
                #pragma unroll
                for (int c = 0; c < 4; ++c) c1[a][b][c] = 0.f;

        #pragma unroll
        for (int kk = 0; kk < 16; ++kk) {
            uint32_t fa[8], fb[4];
            ldsm4(aX + kk * 32, fa);
            ldsm4(aX + 16 * PX + kk * 32, fa + 4);
            ldsm4(aW1 + kk * 32, fb);
            mma16816(c1[0][0], fa + 0, fb[0], fb[2]);
            mma16816(c1[0][1], fa + 0, fb[1], fb[3]);
            mma16816(c1[1][0], fa + 4, fb[0], fb[2]);
            mma16816(c1[1][1], fa + 4, fb[1], fb[3]);
        }
        __syncthreads();
        if (j < 15) {
            stage64(sb + SM_W1H, g_w1h + ((size_t)e * HH + (j + 1) * 64) * DD, tid);
            CP_COMMIT();
        }

        // ---- activation, in place (undo x64 weight scale) ----
        if (isKan) {
            #pragma unroll
            for (int a = 0; a < 2; ++a)
                #pragma unroll
                for (int b = 0; b < 2; ++b)
                    #pragma unroll
                    for (int c = 0; c < 4; ++c)
                        c1[a][b][c] = fast_tanh(c1[a][b][c] * WSCI);
        } else {
            #pragma unroll
            for (int nt = 0; nt < 2; ++nt) {
                int col = j * 64 + 16 * wn + 8 * nt + 2 * (lane & 3);
                float2 bv = *(const float2*)(mlp_b1 + (size_t)m * HH + col);
                #pragma unroll
                for (int a = 0; a < 2; ++a) {
                    c1[a][nt][0] = gelu_tanh(c1[a][nt][0] * WSCI + bv.x);
                    c1[a][nt][1] = gelu_tanh(c1[a][nt][1] * WSCI + bv.y);
                    c1[a][nt][2] = gelu_tanh(c1[a][nt][2] * WSCI + bv.x);
                    c1[a][nt][3] = gelu_tanh(c1[a][nt][3] * WSCI + bv.y);
                }
            }
        }

        for (int p = 1; p <= npoly; ++p) {
            #pragma unroll
            for (int a = 0; a < 2; ++a)
                #pragma unroll
                for (int nt = 0; nt < 2; ++nt) {
                    float v[4];
                    #pragma unroll
                    for (int c = 0; c < 4; ++c) {
                        float t = c1[a][nt][c];
                        v[c] = (p == 1) ? t
                             : (p == 2) ? fmaf(2.f * t, t, -1.f)
                                        : t * fmaf(4.f * t, t, -3.f);
                    }
                    int rowb = 32 * wm + 16 * a + (lane >> 2);
                    int colb = (16 * wn + 8 * nt + 2 * (lane & 3)) * 2;
                    *(__half2*)(smc + SM_A + rowb * PW2 + colb) = __floats2half2_rn(v[0], v[1]);
                    *(__half2*)(smc + SM_A + (rowb + 8) * PW2 + colb) = __floats2half2_rn(v[2], v[3]);
                }

            #pragma unroll
            for (int sub = 0; sub < 2; ++sub) {
                int s = (p - 1) * 2 + sub;
                if (s < 2) { CP_WAIT(2); } else { CP_WAIT(1); }
                __syncthreads();
                const uint32_t w2b = aW2 + sub * 18432;
                #pragma unroll
                for (int kk = 0; kk < 4; ++kk) {
                    uint32_t Fa[8], Fb[8];
                    ldsm4(aA + kk * 32, Fa);
                    ldsm4(aA + 16 * PW2 + kk * 32, Fa + 4);
                    ldsm4(w2b + kk * 32, Fb);
                    ldsm4(w2b + 16 * PW2 + kk * 32, Fb + 4);
                    #pragma unroll
                    for (int a = 0; a < 2; ++a)
                        #pragma unroll
                        for (int nt = 0; nt < 4; ++nt)
                            mma16816(acc[sub][a][nt], Fa + a * 4,
                                     Fb[4 * (nt >> 1) + (nt & 1)],
                                     Fb[4 * (nt >> 1) + (nt & 1) + 2]);
                }
                __syncthreads();
                int ss = s + 2;
                if (ss < ns) { stage_w2(sb, j, ss, isKan, e, m, tid); CP_COMMIT(); }
                else if (j < 15) { stage_w2(sb, j + 1, ss - ns, isKan, e, m, tid); CP_COMMIT(); }
            }
        }
    }

    // ---- epilogue: out = acc/64 + bias ----
    const float* bp = isKan ? (g_c0 + e * DD) : (mlp_b2 + (size_t)m * DD);
    #pragma unroll
    for (int sub = 0; sub < 2; ++sub)
        #pragma unroll
        for (int a = 0; a < 2; ++a)
            #pragma unroll
            for (int nt = 0; nt < 4; ++nt) {
                int row = t0 + 32 * wm + 16 * a + (lane >> 2);
                int col = sub * 128 + 32 * wn + 8 * nt + 2 * (lane & 3);
                float2 v0, v1;
                v0.x = acc[sub][a][nt][0] * WSCI + bp[col];
                v0.y = acc[sub][a][nt][1] * WSCI + bp[col + 1];
                v1.x = acc[sub][a][nt][2] * WSCI + bp[col];
                v1.y = acc[sub][a][nt][3] * WSCI + bp[col + 1];
                *(float2*)(out + (size_t)row * DMODEL + e * DD + col) = v0;
                *(float2*)(out + (size_t)(row + 8) * DMODEL + e * DD + col) = v1;
            }
}

extern "C" void kernel_launch(void* const* d_in, const int* in_sizes, int n_in,
                              void* d_out, int out_size) {
    const float* x   = (const float*)d_in[0];
    const float* klw = (const float*)d_in[1];
    const float* kpw = (const float*)d_in[2];
    const float* kb  = (const float*)d_in[3];
    const float* w1  = (const float*)d_in[4];
    const float* b1  = (const float*)d_in[5];
    const float* w2  = (const float*)d_in[6];
    const float* b2  = (const float*)d_in[7];
    float* out = (float*)d_out;

    cudaFuncSetAttribute(ffn_mma, cudaFuncAttributeMaxDynamicSharedMemorySize, SM_TOTAL);

    c0_kernel<<<NKAN, DD>>>(kpw, kb);
    xhalf<<<TOK * DMODEL / 1024, 256>>>(x);
    tconv_w1<<<dim3(DD / 32, HH / 32, EEXP), dim3(32, 8)>>>(klw, w1);
    tconv_w2m<<<dim3(HH / 32, DD / 32, 6), dim3(32, 8)>>>(w2);
    tconv_w2k<<<dim3(HH / 32, DD / 32, 6), dim3(32, 8)>>>(kpw);
    ffn_mma<<<dim3(TOK / MT, EEXP), NTHR, SM_TOTAL>>>(b1, b2, out);
}